// round 1
// baseline (speedup 1.0000x reference)
#include <cuda_runtime.h>
#include <math.h>

// Problem constants (RG_LRU: B=4, T=8192, D=1024, C=8)
#define B_ 4
#define T_ 8192
#define D_ 1024
#define M_ (B_ * T_)          // 32768 rows

// GEMM tiling
#define BM 128
#define BN 64
#define BK 16

// Scan chunking
#define NCHUNK 32
#define TC (T_ / NCHUNK)      // 256
#define NCH (B_ * D_)         // 4096 channels

// Scratch (device globals: allocation-free per harness rules)
__device__ float g_alpha[(size_t)M_ * D_];   // 128 MB
__device__ float g_xbeta[(size_t)M_ * D_];   // 128 MB
__device__ float g_Ac[NCHUNK * NCH];
__device__ float g_Bc[NCHUNK * NCH];
__device__ float g_carry[NCHUNK * NCH];

__device__ __forceinline__ float sigm(float v) {
    return 1.0f / (1.0f + __expf(-v));
}

// Fused dual-GEMM + gate epilogue:
//   ig = x @ W_in^T + b_in ; rg = x @ W_gate^T + b_gate
//   alpha = exp(-8*softplus(lambda)*sigmoid(rg))
//   xbeta = sqrt(1-alpha^2+1e-6) * sigmoid(ig) * x
// Writes g_alpha, g_xbeta.
__global__ void __launch_bounds__(256, 2)
gates_gemm(const float* __restrict__ x,
           const float* __restrict__ Win, const float* __restrict__ bin,
           const float* __restrict__ Wg,  const float* __restrict__ bgt,
           const float* __restrict__ lam)
{
    // Padded to avoid STS bank conflicts; row strides keep float4 LDS 16B-aligned.
    __shared__ float As[BK][132];
    __shared__ float Bi[BK][68];
    __shared__ float Bg[BK][68];

    const int tid = threadIdx.x;
    const int tx = tid & 15;           // column group (0..15) -> 4 cols each
    const int ty = tid >> 4;           // row group (0..15)    -> 8 rows, stride 16
    const int m0 = blockIdx.y * BM;
    const int n0 = blockIdx.x * BN;

    float acc_i[8][4], acc_g[8][4];
#pragma unroll
    for (int i = 0; i < 8; i++)
#pragma unroll
        for (int j = 0; j < 4; j++) { acc_i[i][j] = 0.0f; acc_g[i][j] = 0.0f; }

    const int lrow = tid >> 2;         // 0..63
    const int lc4  = tid & 3;          // 0..3 (which float4 along K)

    const float* xA0 = x   + (size_t)(m0 + lrow)      * D_ + lc4 * 4;
    const float* xA1 = x   + (size_t)(m0 + lrow + 64) * D_ + lc4 * 4;
    const float* wiP = Win + (size_t)(n0 + lrow)      * D_ + lc4 * 4;
    const float* wgP = Wg  + (size_t)(n0 + lrow)      * D_ + lc4 * 4;

    for (int k0 = 0; k0 < D_; k0 += BK) {
        float4 va0 = *(const float4*)(xA0 + k0);
        float4 va1 = *(const float4*)(xA1 + k0);
        float4 vi  = *(const float4*)(wiP + k0);
        float4 vg  = *(const float4*)(wgP + k0);

        As[lc4 * 4 + 0][lrow] = va0.x;
        As[lc4 * 4 + 1][lrow] = va0.y;
        As[lc4 * 4 + 2][lrow] = va0.z;
        As[lc4 * 4 + 3][lrow] = va0.w;
        As[lc4 * 4 + 0][lrow + 64] = va1.x;
        As[lc4 * 4 + 1][lrow + 64] = va1.y;
        As[lc4 * 4 + 2][lrow + 64] = va1.z;
        As[lc4 * 4 + 3][lrow + 64] = va1.w;

        Bi[lc4 * 4 + 0][lrow] = vi.x;
        Bi[lc4 * 4 + 1][lrow] = vi.y;
        Bi[lc4 * 4 + 2][lrow] = vi.z;
        Bi[lc4 * 4 + 3][lrow] = vi.w;

        Bg[lc4 * 4 + 0][lrow] = vg.x;
        Bg[lc4 * 4 + 1][lrow] = vg.y;
        Bg[lc4 * 4 + 2][lrow] = vg.z;
        Bg[lc4 * 4 + 3][lrow] = vg.w;

        __syncthreads();

#pragma unroll
        for (int kk = 0; kk < BK; kk++) {
            float a[8], fi[4], fg[4];
#pragma unroll
            for (int i = 0; i < 8; i++) a[i] = As[kk][ty + i * 16];
            float4 fi4 = *(const float4*)&Bi[kk][tx * 4];
            float4 fg4 = *(const float4*)&Bg[kk][tx * 4];
            fi[0] = fi4.x; fi[1] = fi4.y; fi[2] = fi4.z; fi[3] = fi4.w;
            fg[0] = fg4.x; fg[1] = fg4.y; fg[2] = fg4.z; fg[3] = fg4.w;
#pragma unroll
            for (int i = 0; i < 8; i++) {
#pragma unroll
                for (int j = 0; j < 4; j++) {
                    acc_i[i][j] = fmaf(a[i], fi[j], acc_i[i][j]);
                    acc_g[i][j] = fmaf(a[i], fg[j], acc_g[i][j]);
                }
            }
        }
        __syncthreads();
    }

    // Epilogue: gate math, write alpha/xbeta (float4, coalesced).
    const int dbase = n0 + tx * 4;
    float cl[4], bib[4], bgb[4];
#pragma unroll
    for (int j = 0; j < 4; j++) {
        float l = lam[dbase + j];
        cl[j]  = 8.0f * log1pf(expf(l));  // C * softplus(lambda)
        bib[j] = bin[dbase + j];
        bgb[j] = bgt[dbase + j];
    }

#pragma unroll
    for (int i = 0; i < 8; i++) {
        const int m = m0 + ty + i * 16;
        const size_t orow = (size_t)m * D_ + dbase;
        float4 xv = *(const float4*)(x + orow);
        float xa[4] = { xv.x, xv.y, xv.z, xv.w };
        float av[4], bv[4];
#pragma unroll
        for (int j = 0; j < 4; j++) {
            float ig = acc_i[i][j] + bib[j];
            float rg = acc_g[i][j] + bgb[j];
            float sr = sigm(rg);
            float al = __expf(-cl[j] * sr);
            float be = sqrtf(fmaxf(1.0f - al * al + 1e-6f, 0.0f));
            av[j] = al;
            bv[j] = be * sigm(ig) * xa[j];
        }
        *(float4*)(g_alpha + orow) = make_float4(av[0], av[1], av[2], av[3]);
        *(float4*)(g_xbeta + orow) = make_float4(bv[0], bv[1], bv[2], bv[3]);
    }
}

// Phase 1: per-chunk aggregates (A = prod alpha, Bv = local scan end value)
__global__ void __launch_bounds__(256)
scan_chunks()
{
    const int tid = threadIdx.x;
    const int bid = blockIdx.x;         // 0 .. NCHUNK*(NCH/256)-1
    const int chunk = bid >> 4;         // / (NCH/256)=16
    const int seg   = bid & 15;
    const int ch = seg * 256 + tid;     // 0..4095
    const int b = ch >> 10;
    const int d = ch & (D_ - 1);

    size_t idx = ((size_t)b * T_ + (size_t)chunk * TC) * D_ + d;
    float A = 1.0f, Bv = 0.0f;
#pragma unroll 4
    for (int t = 0; t < TC; t++) {
        float a = g_alpha[idx];
        float v = g_xbeta[idx];
        Bv = fmaf(a, Bv, v);
        A *= a;
        idx += D_;
    }
    g_Ac[chunk * NCH + ch] = A;
    g_Bc[chunk * NCH + ch] = Bv;
}

// Phase 2: exclusive scan of chunk aggregates per channel -> carry-in per chunk
__global__ void __launch_bounds__(256)
scan_carry()
{
    const int ch = blockIdx.x * 256 + threadIdx.x;   // 16 blocks
    float h = 0.0f;
#pragma unroll
    for (int c = 0; c < NCHUNK; c++) {
        g_carry[c * NCH + ch] = h;
        h = fmaf(g_Ac[c * NCH + ch], h, g_Bc[c * NCH + ch]);
    }
}

// Phase 3: re-run local scan with carry-in, write h
__global__ void __launch_bounds__(256)
scan_apply(float* __restrict__ out)
{
    const int tid = threadIdx.x;
    const int bid = blockIdx.x;
    const int chunk = bid >> 4;
    const int seg   = bid & 15;
    const int ch = seg * 256 + tid;
    const int b = ch >> 10;
    const int d = ch & (D_ - 1);

    size_t idx = ((size_t)b * T_ + (size_t)chunk * TC) * D_ + d;
    float h = g_carry[chunk * NCH + ch];
#pragma unroll 4
    for (int t = 0; t < TC; t++) {
        float a = g_alpha[idx];
        float v = g_xbeta[idx];
        h = fmaf(a, h, v);
        out[idx] = h;
        idx += D_;
    }
}

extern "C" void kernel_launch(void* const* d_in, const int* in_sizes, int n_in,
                              void* d_out, int out_size)
{
    const float* x   = (const float*)d_in[0];
    const float* Win = (const float*)d_in[1];
    const float* bin = (const float*)d_in[2];
    const float* Wg  = (const float*)d_in[3];
    const float* bgt = (const float*)d_in[4];
    const float* lam = (const float*)d_in[5];
    float* out = (float*)d_out;

    dim3 ggrid(D_ / BN, M_ / BM);   // (16, 256)
    gates_gemm<<<ggrid, 256>>>(x, Win, bin, Wg, bgt, lam);

    scan_chunks<<<NCHUNK * (NCH / 256), 256>>>();
    scan_carry<<<NCH / 256, 256>>>();
    scan_apply<<<NCHUNK * (NCH / 256), 256>>>(out);
}

// round 3
// speedup vs baseline: 2.2218x; 2.2218x over previous
#include <cuda_runtime.h>
#include <cuda_bf16.h>
#include <math.h>
#include <stdint.h>

// Problem constants (RG_LRU: B=4, T=8192, D=1024, C=8)
#define B_ 4
#define T_ 8192
#define D_ 1024
#define M_ (B_ * T_)          // 32768 rows

// Scan chunking
#define NCHUNK 32
#define TC (T_ / NCHUNK)      // 256
#define NCH (B_ * D_)         // 4096 channels

// GEMM tiling
#define BM 128
#define BN 64
#define BK 64                 // bf16 per K-tile = 128 B rows (SW128 atom)
#define KT (D_ / BK)          // 16

// smem stage layout (bytes)
#define OFF_XH  0
#define OFF_XL  16384
#define OFF_WIH 32768
#define OFF_WIL 40960
#define OFF_WGH 49152
#define OFF_WGL 57344
#define STAGE_SZ 65536
#define NSTAGE 3
#define PAR_OFF (NSTAGE * STAGE_SZ)          // gate params: 3 x 64 floats
#define SMEM_DYN (PAR_OFF + 1024 + 1024)

// ---------------- device scratch (allocation-free) ----------------
__device__ float g_alpha[(size_t)M_ * D_];       // 128 MB
__device__ float g_xbeta[(size_t)M_ * D_];       // 128 MB
__device__ float g_Ac[NCHUNK * NCH];
__device__ float g_Bc[NCHUNK * NCH];
__device__ float g_carry[NCHUNK * NCH];
__device__ __nv_bfloat16 g_xhi[(size_t)M_ * D_]; // 64 MB
__device__ __nv_bfloat16 g_xlo[(size_t)M_ * D_]; // 64 MB
__device__ __nv_bfloat16 g_wih[D_ * D_];
__device__ __nv_bfloat16 g_wil[D_ * D_];
__device__ __nv_bfloat16 g_wgh[D_ * D_];
__device__ __nv_bfloat16 g_wgl[D_ * D_];

// ---------------- helpers ----------------
__device__ __forceinline__ uint32_t smem_u32(const void* p) {
    uint32_t a;
    asm("{ .reg .u64 t; cvta.to.shared.u64 t, %1; cvt.u32.u64 %0, t; }" : "=r"(a) : "l"(p));
    return a;
}
__device__ __forceinline__ void cp16(uint32_t dst, const void* src) {
    asm volatile("cp.async.cg.shared.global [%0], [%1], 16;" :: "r"(dst), "l"(src));
}
#define CP_COMMIT() asm volatile("cp.async.commit_group;" ::: "memory")
#define CP_WAIT(n)  asm volatile("cp.async.wait_group %0;" :: "n"(n) : "memory")

__device__ __forceinline__ void ldsm4(uint32_t addr, uint32_t& r0, uint32_t& r1,
                                      uint32_t& r2, uint32_t& r3) {
    asm volatile("ldmatrix.sync.aligned.m8n8.x4.shared.b16 {%0,%1,%2,%3}, [%4];"
                 : "=r"(r0), "=r"(r1), "=r"(r2), "=r"(r3) : "r"(addr));
}
__device__ __forceinline__ void mma16816(float* d, const uint32_t* a, const uint32_t* b) {
    asm volatile("mma.sync.aligned.m16n8k16.row.col.f32.bf16.bf16.f32 "
                 "{%0,%1,%2,%3}, {%4,%5,%6,%7}, {%8,%9}, {%0,%1,%2,%3};"
                 : "+f"(d[0]), "+f"(d[1]), "+f"(d[2]), "+f"(d[3])
                 : "r"(a[0]), "r"(a[1]), "r"(a[2]), "r"(a[3]), "r"(b[0]), "r"(b[1]));
}
__device__ __forceinline__ float sigm(float v) { return 1.0f / (1.0f + __expf(-v)); }

// ---------------- fp32 -> bf16 hi/lo split ----------------
__device__ __forceinline__ void split1(float v, unsigned short& h, unsigned short& l) {
    __nv_bfloat16 hb = __float2bfloat16(v);
    float r = v - __bfloat162float(hb);
    __nv_bfloat16 lb = __float2bfloat16(r);
    h = __bfloat16_as_ushort(hb);
    l = __bfloat16_as_ushort(lb);
}

__global__ void __launch_bounds__(256)
conv_x(const float* __restrict__ x)
{
    size_t i = (size_t)blockIdx.x * 256 + threadIdx.x;   // float4 index
    float4 v = ((const float4*)x)[i];
    ushort4 h, l;
    split1(v.x, h.x, l.x); split1(v.y, h.y, l.y);
    split1(v.z, h.z, l.z); split1(v.w, h.w, l.w);
    ((ushort4*)g_xhi)[i] = h;
    ((ushort4*)g_xlo)[i] = l;
}

__global__ void __launch_bounds__(256)
conv_w(const float* __restrict__ wi, const float* __restrict__ wg)
{
    size_t i = (size_t)blockIdx.x * 256 + threadIdx.x;
    float4 a = ((const float4*)wi)[i];
    float4 b = ((const float4*)wg)[i];
    ushort4 h, l;
    split1(a.x, h.x, l.x); split1(a.y, h.y, l.y);
    split1(a.z, h.z, l.z); split1(a.w, h.w, l.w);
    ((ushort4*)g_wih)[i] = h; ((ushort4*)g_wil)[i] = l;
    split1(b.x, h.x, l.x); split1(b.y, h.y, l.y);
    split1(b.z, h.z, l.z); split1(b.w, h.w, l.w);
    ((ushort4*)g_wgh)[i] = h; ((ushort4*)g_wgl)[i] = l;
}

// ---------------- stage loader: gmem -> SW128-swizzled smem ----------------
__device__ __forceinline__ void ld_stage(uint32_t sbase, int kt, int m0, int n0, int tid)
{
    const int k0 = kt * BK;
#pragma unroll
    for (int i = 0; i < 4; i++) {            // x tiles: 128 rows x 8 chunks
        int q = tid + i * 256;
        int r = q >> 3, c = q & 7;
        uint32_t off = (uint32_t)(r * 128 + (((c ^ (r & 7))) << 4));
        size_t gi = (size_t)(m0 + r) * D_ + k0 + c * 8;
        cp16(sbase + OFF_XH + off, g_xhi + gi);
        cp16(sbase + OFF_XL + off, g_xlo + gi);
    }
#pragma unroll
    for (int i = 0; i < 2; i++) {            // W tiles: 64 rows x 8 chunks
        int q = tid + i * 256;
        int r = q >> 3, c = q & 7;
        uint32_t off = (uint32_t)(r * 128 + (((c ^ (r & 7))) << 4));
        size_t gi = (size_t)(n0 + r) * D_ + k0 + c * 8;
        cp16(sbase + OFF_WIH + off, g_wih + gi);
        cp16(sbase + OFF_WIL + off, g_wil + gi);
        cp16(sbase + OFF_WGH + off, g_wgh + gi);
        cp16(sbase + OFF_WGL + off, g_wgl + gi);
    }
}

// ---------------- fused dual-GEMM (HMMA bf16x3) + gate epilogue ----------------
__global__ void __launch_bounds__(256, 1)
gates_gemm_hmma(const float* __restrict__ x,
                const float* __restrict__ bin, const float* __restrict__ bgt,
                const float* __restrict__ lam)
{
    extern __shared__ char smem_raw[];
    char* smem = (char*)(((uintptr_t)smem_raw + 1023) & ~(uintptr_t)1023);
    const uint32_t sb = smem_u32(smem);
    const int tid = threadIdx.x;
    const int lane = tid & 31;
    const int wid = tid >> 5;
    const int wm = wid >> 1;                 // 0..3
    const int wn = wid & 1;                  // 0..1
    const int m0 = blockIdx.y * BM;
    const int n0 = blockIdx.x * BN;

    float* cl_s = (float*)(smem + PAR_OFF);
    float* bi_s = cl_s + 64;
    float* bg_s = bi_s + 64;
    if (tid < 64) {
        float l = lam[n0 + tid];
        cl_s[tid] = 8.0f * log1pf(expf(l));  // C * softplus(lambda)
        bi_s[tid] = bin[n0 + tid];
        bg_s[tid] = bgt[n0 + tid];
    }

    // accumulators: [mb][nb][4]
    float aig[2][4][4], arg[2][4][4];
#pragma unroll
    for (int mb = 0; mb < 2; mb++)
#pragma unroll
        for (int nb = 0; nb < 4; nb++)
#pragma unroll
            for (int q = 0; q < 4; q++) { aig[mb][nb][q] = 0.f; arg[mb][nb][q] = 0.f; }

    // per-thread ldmatrix row mapping
    const int r16 = (lane & 7) | (((lane >> 3) & 1) << 3);  // row within 16
    const int coff = lane >> 4;                             // k-chunk offset 0/1
    int arow[2], brow[2];
#pragma unroll
    for (int mb = 0; mb < 2; mb++) arow[mb] = wm * 32 + mb * 16 + r16;
#pragma unroll
    for (int j = 0; j < 2; j++)    brow[j] = wn * 32 + j * 16 + r16;

    // prologue: fill pipeline
#pragma unroll
    for (int s = 0; s < NSTAGE; s++) { ld_stage(sb + s * STAGE_SZ, s, m0, n0, tid); CP_COMMIT(); }

    for (int kt = 0; kt < KT; kt++) {
        const int st = kt % NSTAGE;
        const uint32_t stb = sb + st * STAGE_SZ;
        CP_WAIT(NSTAGE - 1);
        __syncthreads();

#pragma unroll
        for (int k16 = 0; k16 < 4; k16++) {
            const int chunk = k16 * 2 + coff;
            uint32_t axh[2][4], axl[2][4];
#pragma unroll
            for (int mb = 0; mb < 2; mb++) {
                uint32_t off = (uint32_t)(arow[mb] * 128 + ((chunk ^ (arow[mb] & 7)) << 4));
                ldsm4(stb + OFF_XH + off, axh[mb][0], axh[mb][1], axh[mb][2], axh[mb][3]);
                ldsm4(stb + OFF_XL + off, axl[mb][0], axl[mb][1], axl[mb][2], axl[mb][3]);
            }
            uint32_t bw[4][4][2];            // [wmat: ih,il,gh,gl][nb][2]
            const uint32_t woffs[4] = { OFF_WIH, OFF_WIL, OFF_WGH, OFF_WGL };
#pragma unroll
            for (int wmx = 0; wmx < 4; wmx++) {
#pragma unroll
                for (int j = 0; j < 2; j++) {
                    uint32_t off = (uint32_t)(brow[j] * 128 + ((chunk ^ (brow[j] & 7)) << 4));
                    uint32_t r0, r1, r2, r3;
                    ldsm4(stb + woffs[wmx] + off, r0, r1, r2, r3);
                    bw[wmx][j * 2 + 0][0] = r0; bw[wmx][j * 2 + 0][1] = r2;
                    bw[wmx][j * 2 + 1][0] = r1; bw[wmx][j * 2 + 1][1] = r3;
                }
            }
#pragma unroll
            for (int mb = 0; mb < 2; mb++) {
#pragma unroll
                for (int nb = 0; nb < 4; nb++) {
                    mma16816(aig[mb][nb], axh[mb], bw[0][nb]);   // xh * Wih
                    mma16816(aig[mb][nb], axl[mb], bw[0][nb]);   // xl * Wih
                    mma16816(aig[mb][nb], axh[mb], bw[1][nb]);   // xh * Wil
                    mma16816(arg[mb][nb], axh[mb], bw[2][nb]);   // xh * Wgh
                    mma16816(arg[mb][nb], axl[mb], bw[2][nb]);   // xl * Wgh
                    mma16816(arg[mb][nb], axh[mb], bw[3][nb]);   // xh * Wgl
                }
            }
        }
        __syncthreads();
        const int nk = kt + NSTAGE;
        if (nk < KT) { ld_stage(stb, nk, m0, n0, tid); CP_COMMIT(); }
    }

    // ---------------- epilogue: gate math + store alpha/xbeta ----------------
    const int g = lane >> 2;
    const int t2 = 2 * (lane & 3);
#pragma unroll
    for (int mb = 0; mb < 2; mb++) {
#pragma unroll
        for (int half = 0; half < 2; half++) {            // row g vs g+8 (regs 0,1 vs 2,3)
            const int row = m0 + wm * 32 + mb * 16 + g + half * 8;
#pragma unroll
            for (int nb = 0; nb < 4; nb++) {
                const int cloc = wn * 32 + nb * 8 + t2;
                const size_t gi = (size_t)row * D_ + n0 + cloc;
                float2 xv = *(const float2*)(x + gi);
                float a2[2], v2[2];
#pragma unroll
                for (int q = 0; q < 2; q++) {
                    float ig = aig[mb][nb][half * 2 + q] + bi_s[cloc + q];
                    float rg = arg[mb][nb][half * 2 + q] + bg_s[cloc + q];
                    float sr = sigm(rg);
                    float al = __expf(-cl_s[cloc + q] * sr);
                    float be = sqrtf(fmaxf(1.0f - al * al + 1e-6f, 0.0f));
                    a2[q] = al;
                    v2[q] = be * sigm(ig) * ((q == 0) ? xv.x : xv.y);
                }
                *(float2*)(g_alpha + gi) = make_float2(a2[0], a2[1]);
                *(float2*)(g_xbeta + gi) = make_float2(v2[0], v2[1]);
            }
        }
    }
}

// ---------------- scan (near-roofline; unchanged) ----------------
__global__ void __launch_bounds__(256)
scan_chunks()
{
    const int tid = threadIdx.x;
    const int bid = blockIdx.x;
    const int chunk = bid >> 4;
    const int seg   = bid & 15;
    const int ch = seg * 256 + tid;
    const int b = ch >> 10;
    const int d = ch & (D_ - 1);

    size_t idx = ((size_t)b * T_ + (size_t)chunk * TC) * D_ + d;
    float A = 1.0f, Bv = 0.0f;
#pragma unroll 4
    for (int t = 0; t < TC; t++) {
        float a = g_alpha[idx];
        float v = g_xbeta[idx];
        Bv = fmaf(a, Bv, v);
        A *= a;
        idx += D_;
    }
    g_Ac[chunk * NCH + ch] = A;
    g_Bc[chunk * NCH + ch] = Bv;
}

__global__ void __launch_bounds__(256)
scan_carry()
{
    const int ch = blockIdx.x * 256 + threadIdx.x;
    float h = 0.0f;
#pragma unroll
    for (int c = 0; c < NCHUNK; c++) {
        g_carry[c * NCH + ch] = h;
        h = fmaf(g_Ac[c * NCH + ch], h, g_Bc[c * NCH + ch]);
    }
}

__global__ void __launch_bounds__(256)
scan_apply(float* __restrict__ out)
{
    const int tid = threadIdx.x;
    const int bid = blockIdx.x;
    const int chunk = bid >> 4;
    const int seg   = bid & 15;
    const int ch = seg * 256 + tid;
    const int b = ch >> 10;
    const int d = ch & (D_ - 1);

    size_t idx = ((size_t)b * T_ + (size_t)chunk * TC) * D_ + d;
    float h = g_carry[chunk * NCH + ch];
#pragma unroll 4
    for (int t = 0; t < TC; t++) {
        float a = g_alpha[idx];
        float v = g_xbeta[idx];
        h = fmaf(a, h, v);
        out[idx] = h;
        idx += D_;
    }
}

// ---------------- launch ----------------
extern "C" void kernel_launch(void* const* d_in, const int* in_sizes, int n_in,
                              void* d_out, int out_size)
{
    const float* x   = (const float*)d_in[0];
    const float* Win = (const float*)d_in[1];
    const float* bin = (const float*)d_in[2];
    const float* Wg  = (const float*)d_in[3];
    const float* bgt = (const float*)d_in[4];
    const float* lam = (const float*)d_in[5];
    float* out = (float*)d_out;

    cudaFuncSetAttribute(gates_gemm_hmma, cudaFuncAttributeMaxDynamicSharedMemorySize, SMEM_DYN);

    conv_x<<<(M_ * (D_ / 4)) / 256, 256>>>(x);
    conv_w<<<(D_ * (D_ / 4)) / 256, 256>>>(Win, Wg);

    dim3 ggrid(D_ / BN, M_ / BM);                // (16, 256)
    gates_gemm_hmma<<<ggrid, 256, SMEM_DYN>>>(x, bin, bgt, lam);

    scan_chunks<<<NCHUNK * (NCH / 256), 256>>>();
    scan_carry<<<NCH / 256, 256>>>();
    scan_apply<<<NCHUNK * (NCH / 256), 256>>>(out);
}

// round 4
// speedup vs baseline: 2.3210x; 1.0446x over previous
#include <cuda_runtime.h>
#include <cuda_bf16.h>
#include <math.h>
#include <stdint.h>

// Problem constants (RG_LRU: B=4, T=8192, D=1024, C=8)
#define B_ 4
#define T_ 8192
#define D_ 1024
#define M_ (B_ * T_)          // 32768 rows

// Scan chunking
#define NCHUNK 32
#define TC (T_ / NCHUNK)      // 256
#define NCH (B_ * D_)         // 4096 channels

// GEMM tiling
#define BM 128
#define BN 64
#define BK 32                 // bf16 per K-tile = 64 B rows (SW64 atom)
#define KT (D_ / BK)          // 32

// smem stage layout (bytes): x tiles 128x64B = 8KB, W tiles 64x64B = 4KB
#define OFF_XH  0
#define OFF_XL  8192
#define OFF_WIH 16384
#define OFF_WIL 20480
#define OFF_WGH 24576
#define OFF_WGL 28672
#define STAGE_SZ 32768
#define NSTAGE 3
#define PAR_OFF (NSTAGE * STAGE_SZ)          // gate params: 3 x 64 floats
#define SMEM_DYN (PAR_OFF + 1024 + 1024)     // ~98 KB -> 2 CTAs/SM

// ---------------- device scratch (allocation-free) ----------------
__device__ float g_alpha[(size_t)M_ * D_];       // 128 MB
__device__ float g_xbeta[(size_t)M_ * D_];       // 128 MB
__device__ float g_Ac[NCHUNK * NCH];
__device__ float g_Bc[NCHUNK * NCH];
__device__ float g_carry[NCHUNK * NCH];
__device__ __nv_bfloat16 g_xhi[(size_t)M_ * D_]; // 64 MB
__device__ __nv_bfloat16 g_xlo[(size_t)M_ * D_]; // 64 MB
__device__ __nv_bfloat16 g_wih[D_ * D_];
__device__ __nv_bfloat16 g_wil[D_ * D_];
__device__ __nv_bfloat16 g_wgh[D_ * D_];
__device__ __nv_bfloat16 g_wgl[D_ * D_];

// ---------------- helpers ----------------
__device__ __forceinline__ uint32_t smem_u32(const void* p) {
    uint32_t a;
    asm("{ .reg .u64 t; cvta.to.shared.u64 t, %1; cvt.u32.u64 %0, t; }" : "=r"(a) : "l"(p));
    return a;
}
__device__ __forceinline__ void cp16(uint32_t dst, const void* src) {
    asm volatile("cp.async.cg.shared.global [%0], [%1], 16;" :: "r"(dst), "l"(src));
}
#define CP_COMMIT() asm volatile("cp.async.commit_group;" ::: "memory")
#define CP_WAIT(n)  asm volatile("cp.async.wait_group %0;" :: "n"(n) : "memory")

__device__ __forceinline__ void ldsm4(uint32_t addr, uint32_t& r0, uint32_t& r1,
                                      uint32_t& r2, uint32_t& r3) {
    asm volatile("ldmatrix.sync.aligned.m8n8.x4.shared.b16 {%0,%1,%2,%3}, [%4];"
                 : "=r"(r0), "=r"(r1), "=r"(r2), "=r"(r3) : "r"(addr));
}
__device__ __forceinline__ void mma16816(float* d, const uint32_t* a, const uint32_t* b) {
    asm volatile("mma.sync.aligned.m16n8k16.row.col.f32.bf16.bf16.f32 "
                 "{%0,%1,%2,%3}, {%4,%5,%6,%7}, {%8,%9}, {%0,%1,%2,%3};"
                 : "+f"(d[0]), "+f"(d[1]), "+f"(d[2]), "+f"(d[3])
                 : "r"(a[0]), "r"(a[1]), "r"(a[2]), "r"(a[3]), "r"(b[0]), "r"(b[1]));
}
__device__ __forceinline__ float sigm(float v) { return 1.0f / (1.0f + __expf(-v)); }

// SW64 swizzle for 64B rows: chunk c (16B) at row r -> c ^ ((r>>1)&3)
__device__ __forceinline__ uint32_t sw64_off(int r, int c) {
    return (uint32_t)(r * 64 + ((c ^ ((r >> 1) & 3)) << 4));
}

// ---------------- fp32 -> bf16 hi/lo split ----------------
__device__ __forceinline__ void split1(float v, unsigned short& h, unsigned short& l) {
    __nv_bfloat16 hb = __float2bfloat16(v);
    float r = v - __bfloat162float(hb);
    __nv_bfloat16 lb = __float2bfloat16(r);
    h = __bfloat16_as_ushort(hb);
    l = __bfloat16_as_ushort(lb);
}

__global__ void __launch_bounds__(256)
conv_x(const float* __restrict__ x)
{
    size_t i = (size_t)blockIdx.x * 256 + threadIdx.x;   // float4 index
    float4 v = ((const float4*)x)[i];
    ushort4 h, l;
    split1(v.x, h.x, l.x); split1(v.y, h.y, l.y);
    split1(v.z, h.z, l.z); split1(v.w, h.w, l.w);
    ((ushort4*)g_xhi)[i] = h;
    ((ushort4*)g_xlo)[i] = l;
}

__global__ void __launch_bounds__(256)
conv_w(const float* __restrict__ wi, const float* __restrict__ wg)
{
    size_t i = (size_t)blockIdx.x * 256 + threadIdx.x;
    float4 a = ((const float4*)wi)[i];
    float4 b = ((const float4*)wg)[i];
    ushort4 h, l;
    split1(a.x, h.x, l.x); split1(a.y, h.y, l.y);
    split1(a.z, h.z, l.z); split1(a.w, h.w, l.w);
    ((ushort4*)g_wih)[i] = h; ((ushort4*)g_wil)[i] = l;
    split1(b.x, h.x, l.x); split1(b.y, h.y, l.y);
    split1(b.z, h.z, l.z); split1(b.w, h.w, l.w);
    ((ushort4*)g_wgh)[i] = h; ((ushort4*)g_wgl)[i] = l;
}

// ---------------- stage loader: gmem -> SW64-swizzled smem ----------------
__device__ __forceinline__ void ld_stage(uint32_t sbase, int kt, int m0, int n0, int tid)
{
    const int k0 = kt * BK;
#pragma unroll
    for (int i = 0; i < 2; i++) {            // x tiles: 128 rows x 4 chunks
        int q = tid + i * 256;
        int r = q >> 2, c = q & 3;
        uint32_t off = sw64_off(r, c);
        size_t gi = (size_t)(m0 + r) * D_ + k0 + c * 8;
        cp16(sbase + OFF_XH + off, g_xhi + gi);
        cp16(sbase + OFF_XL + off, g_xlo + gi);
    }
    {                                        // W tiles: 64 rows x 4 chunks
        int q = tid;
        int r = q >> 2, c = q & 3;
        uint32_t off = sw64_off(r, c);
        size_t gi = (size_t)(n0 + r) * D_ + k0 + c * 8;
        cp16(sbase + OFF_WIH + off, g_wih + gi);
        cp16(sbase + OFF_WIL + off, g_wil + gi);
        cp16(sbase + OFF_WGH + off, g_wgh + gi);
        cp16(sbase + OFF_WGL + off, g_wgl + gi);
    }
}

// ---------------- fused dual-GEMM (HMMA bf16x3) + gate epilogue ----------------
__global__ void __launch_bounds__(256, 2)
gates_gemm_hmma(const float* __restrict__ x,
                const float* __restrict__ bin, const float* __restrict__ bgt,
                const float* __restrict__ lam)
{
    extern __shared__ char smem_raw[];
    char* smem = (char*)(((uintptr_t)smem_raw + 1023) & ~(uintptr_t)1023);
    const uint32_t sb = smem_u32(smem);
    const int tid = threadIdx.x;
    const int lane = tid & 31;
    const int wid = tid >> 5;
    const int wm = wid >> 1;                 // 0..3
    const int wn = wid & 1;                  // 0..1
    const int m0 = blockIdx.y * BM;
    const int n0 = blockIdx.x * BN;

    float* cl_s = (float*)(smem + PAR_OFF);
    float* bi_s = cl_s + 64;
    float* bg_s = bi_s + 64;
    if (tid < 64) {
        float l = lam[n0 + tid];
        cl_s[tid] = 8.0f * log1pf(expf(l));  // C * softplus(lambda)
        bi_s[tid] = bin[n0 + tid];
        bg_s[tid] = bgt[n0 + tid];
    }

    float aig[2][4][4], arg[2][4][4];
#pragma unroll
    for (int mb = 0; mb < 2; mb++)
#pragma unroll
        for (int nb = 0; nb < 4; nb++)
#pragma unroll
            for (int q = 0; q < 4; q++) { aig[mb][nb][q] = 0.f; arg[mb][nb][q] = 0.f; }

    const int r16 = (lane & 7) | (((lane >> 3) & 1) << 3);  // row within 16
    const int coff = lane >> 4;                             // k-chunk offset 0/1
    int arow[2], brow[2];
#pragma unroll
    for (int mb = 0; mb < 2; mb++) arow[mb] = wm * 32 + mb * 16 + r16;
#pragma unroll
    for (int j = 0; j < 2; j++)    brow[j] = wn * 32 + j * 16 + r16;

    // prologue: fill pipeline
#pragma unroll
    for (int s = 0; s < NSTAGE; s++) { ld_stage(sb + s * STAGE_SZ, s, m0, n0, tid); CP_COMMIT(); }

    for (int kt = 0; kt < KT; kt++) {
        const uint32_t stb = sb + (kt % NSTAGE) * STAGE_SZ;
        CP_WAIT(NSTAGE - 1);
        __syncthreads();

#pragma unroll
        for (int k16 = 0; k16 < 2; k16++) {
            const int chunk = k16 * 2 + coff;
            uint32_t axh[2][4], axl[2][4];
#pragma unroll
            for (int mb = 0; mb < 2; mb++) {
                uint32_t off = sw64_off(arow[mb], chunk);
                ldsm4(stb + OFF_XH + off, axh[mb][0], axh[mb][1], axh[mb][2], axh[mb][3]);
                ldsm4(stb + OFF_XL + off, axl[mb][0], axl[mb][1], axl[mb][2], axl[mb][3]);
            }
            // ---- input gate: Wih (with xh, xl) + Wil (with xh) ----
            {
                uint32_t bh[4][2], bl[4][2];
#pragma unroll
                for (int j = 0; j < 2; j++) {
                    uint32_t off = sw64_off(brow[j], chunk);
                    uint32_t r0, r1, r2, r3;
                    ldsm4(stb + OFF_WIH + off, r0, r1, r2, r3);
                    bh[j * 2 + 0][0] = r0; bh[j * 2 + 0][1] = r2;
                    bh[j * 2 + 1][0] = r1; bh[j * 2 + 1][1] = r3;
                    ldsm4(stb + OFF_WIL + off, r0, r1, r2, r3);
                    bl[j * 2 + 0][0] = r0; bl[j * 2 + 0][1] = r2;
                    bl[j * 2 + 1][0] = r1; bl[j * 2 + 1][1] = r3;
                }
#pragma unroll
                for (int mb = 0; mb < 2; mb++)
#pragma unroll
                    for (int nb = 0; nb < 4; nb++) {
                        mma16816(aig[mb][nb], axh[mb], bh[nb]);
                        mma16816(aig[mb][nb], axl[mb], bh[nb]);
                        mma16816(aig[mb][nb], axh[mb], bl[nb]);
                    }
            }
            // ---- recurrence gate: Wgh (with xh, xl) + Wgl (with xh) ----
            {
                uint32_t bh[4][2], bl[4][2];
#pragma unroll
                for (int j = 0; j < 2; j++) {
                    uint32_t off = sw64_off(brow[j], chunk);
                    uint32_t r0, r1, r2, r3;
                    ldsm4(stb + OFF_WGH + off, r0, r1, r2, r3);
                    bh[j * 2 + 0][0] = r0; bh[j * 2 + 0][1] = r2;
                    bh[j * 2 + 1][0] = r1; bh[j * 2 + 1][1] = r3;
                    ldsm4(stb + OFF_WGL + off, r0, r1, r2, r3);
                    bl[j * 2 + 0][0] = r0; bl[j * 2 + 0][1] = r2;
                    bl[j * 2 + 1][0] = r1; bl[j * 2 + 1][1] = r3;
                }
#pragma unroll
                for (int mb = 0; mb < 2; mb++)
#pragma unroll
                    for (int nb = 0; nb < 4; nb++) {
                        mma16816(arg[mb][nb], axh[mb], bh[nb]);
                        mma16816(arg[mb][nb], axl[mb], bh[nb]);
                        mma16816(arg[mb][nb], axh[mb], bl[nb]);
                    }
            }
        }
        __syncthreads();
        // Always commit a group (possibly empty) so wait_group(NSTAGE-1)
        // always guarantees the consumed stage has landed.
        const int nk = kt + NSTAGE;
        if (nk < KT) ld_stage(stb, nk, m0, n0, tid);
        CP_COMMIT();
    }

    // ---------------- epilogue: gate math + store alpha/xbeta ----------------
    const int g = lane >> 2;
    const int t2 = 2 * (lane & 3);
#pragma unroll
    for (int mb = 0; mb < 2; mb++) {
#pragma unroll
        for (int half = 0; half < 2; half++) {
            const int row = m0 + wm * 32 + mb * 16 + g + half * 8;
#pragma unroll
            for (int nb = 0; nb < 4; nb++) {
                const int cloc = wn * 32 + nb * 8 + t2;
                const size_t gi = (size_t)row * D_ + n0 + cloc;
                float2 xv = *(const float2*)(x + gi);
                float a2[2], v2[2];
#pragma unroll
                for (int q = 0; q < 2; q++) {
                    float ig = aig[mb][nb][half * 2 + q] + bi_s[cloc + q];
                    float rg = arg[mb][nb][half * 2 + q] + bg_s[cloc + q];
                    float sr = sigm(rg);
                    float al = __expf(-cl_s[cloc + q] * sr);
                    float be = sqrtf(fmaxf(1.0f - al * al + 1e-6f, 0.0f));
                    a2[q] = al;
                    v2[q] = be * sigm(ig) * ((q == 0) ? xv.x : xv.y);
                }
                *(float2*)(g_alpha + gi) = make_float2(a2[0], a2[1]);
                *(float2*)(g_xbeta + gi) = make_float2(v2[0], v2[1]);
            }
        }
    }
}

// ---------------- scan kernels (float4, 4 channels/thread) ----------------
__global__ void __launch_bounds__(256)
scan_chunks()
{
    const int gid = blockIdx.x * 256 + threadIdx.x;   // 0 .. 32767
    const int chunk = gid >> 10;                      // / (NCH/4)
    const int c4 = gid & 1023;
    const int b = c4 >> 8;
    const int d = (c4 & 255) * 4;

    size_t fi = (((size_t)b * T_ + (size_t)chunk * TC) * D_ + d) >> 2;  // float4 idx
    float4 A = make_float4(1.f, 1.f, 1.f, 1.f);
    float4 Bv = make_float4(0.f, 0.f, 0.f, 0.f);
#pragma unroll 4
    for (int t = 0; t < TC; t++) {
        float4 a = ((const float4*)g_alpha)[fi];
        float4 v = ((const float4*)g_xbeta)[fi];
        Bv.x = fmaf(a.x, Bv.x, v.x); A.x *= a.x;
        Bv.y = fmaf(a.y, Bv.y, v.y); A.y *= a.y;
        Bv.z = fmaf(a.z, Bv.z, v.z); A.z *= a.z;
        Bv.w = fmaf(a.w, Bv.w, v.w); A.w *= a.w;
        fi += D_ / 4;
    }
    const int ch4 = (chunk * NCH + b * D_ + d) >> 2;
    ((float4*)g_Ac)[ch4] = A;
    ((float4*)g_Bc)[ch4] = Bv;
}

__global__ void __launch_bounds__(256)
scan_carry()
{
    const int c4 = blockIdx.x * 256 + threadIdx.x;    // 0..1023 (NCH/4)
    float4 h = make_float4(0.f, 0.f, 0.f, 0.f);
#pragma unroll
    for (int c = 0; c < NCHUNK; c++) {
        const int i = (c * NCH) / 4 + c4;
        ((float4*)g_carry)[i] = h;
        float4 a = ((const float4*)g_Ac)[i];
        float4 v = ((const float4*)g_Bc)[i];
        h.x = fmaf(a.x, h.x, v.x);
        h.y = fmaf(a.y, h.y, v.y);
        h.z = fmaf(a.z, h.z, v.z);
        h.w = fmaf(a.w, h.w, v.w);
    }
}

__global__ void __launch_bounds__(256)
scan_apply(float* __restrict__ out)
{
    const int gid = blockIdx.x * 256 + threadIdx.x;
    const int chunk = gid >> 10;
    const int c4 = gid & 1023;
    const int b = c4 >> 8;
    const int d = (c4 & 255) * 4;

    size_t fi = (((size_t)b * T_ + (size_t)chunk * TC) * D_ + d) >> 2;
    float4 h = ((const float4*)g_carry)[(chunk * NCH + b * D_ + d) >> 2];
#pragma unroll 4
    for (int t = 0; t < TC; t++) {
        float4 a = ((const float4*)g_alpha)[fi];
        float4 v = ((const float4*)g_xbeta)[fi];
        h.x = fmaf(a.x, h.x, v.x);
        h.y = fmaf(a.y, h.y, v.y);
        h.z = fmaf(a.z, h.z, v.z);
        h.w = fmaf(a.w, h.w, v.w);
        ((float4*)out)[fi] = h;
        fi += D_ / 4;
    }
}

// ---------------- launch ----------------
extern "C" void kernel_launch(void* const* d_in, const int* in_sizes, int n_in,
                              void* d_out, int out_size)
{
    const float* x   = (const float*)d_in[0];
    const float* Win = (const float*)d_in[1];
    const float* bin = (const float*)d_in[2];
    const float* Wg  = (const float*)d_in[3];
    const float* bgt = (const float*)d_in[4];
    const float* lam = (const float*)d_in[5];
    float* out = (float*)d_out;

    cudaFuncSetAttribute(gates_gemm_hmma, cudaFuncAttributeMaxDynamicSharedMemorySize, SMEM_DYN);

    conv_x<<<(M_ * (D_ / 4)) / 256, 256>>>(x);
    conv_w<<<(D_ * (D_ / 4)) / 256, 256>>>(Win, Wg);

    dim3 ggrid(D_ / BN, M_ / BM);                // (16, 256)
    gates_gemm_hmma<<<ggrid, 256, SMEM_DYN>>>(x, bin, bgt, lam);

    scan_chunks<<<128, 256>>>();
    scan_carry<<<NCH / 4 / 256, 256>>>();
    scan_apply<<<128, 256>>>(out);
}

// round 5
// speedup vs baseline: 2.4771x; 1.0673x over previous
#include <cuda_runtime.h>
#include <cuda_bf16.h>
#include <math.h>
#include <stdint.h>

// Problem constants (RG_LRU: B=4, T=8192, D=1024, C=8)
#define B_ 4
#define T_ 8192
#define D_ 1024
#define M_ (B_ * T_)          // 32768 rows

// Scan chunking
#define NCHUNK 128
#define TC (T_ / NCHUNK)      // 64
#define NCH (B_ * D_)         // 4096 channels

// GEMM tiling
#define BM 128
#define BN 64
#define BK 32                 // bf16 per K-tile = 64 B rows (SW64 atom)
#define KT (D_ / BK)          // 32

// smem stage layout (bytes): x tiles 128x64B = 8KB, W tiles 64x64B = 4KB
#define OFF_XH  0
#define OFF_XL  8192
#define OFF_WIH 16384
#define OFF_WIL 20480
#define OFF_WGH 24576
#define OFF_WGL 28672
#define STAGE_SZ 32768
#define NSTAGE 3
#define PAR_OFF (NSTAGE * STAGE_SZ)          // gate params: 3 x 64 floats
#define SMEM_DYN (PAR_OFF + 1024 + 1024)     // ~98 KB -> 2 CTAs/SM

// ---------------- device scratch (allocation-free) ----------------
__device__ float g_alpha[(size_t)M_ * D_];       // 128 MB
__device__ float g_xbeta[(size_t)M_ * D_];       // 128 MB
__device__ float g_Ac[NCHUNK * NCH];
__device__ float g_Bc[NCHUNK * NCH];
__device__ float g_carry[NCHUNK * NCH];
__device__ __nv_bfloat16 g_xhi[(size_t)M_ * D_]; // 64 MB
__device__ __nv_bfloat16 g_xlo[(size_t)M_ * D_]; // 64 MB
__device__ __nv_bfloat16 g_wih[D_ * D_];
__device__ __nv_bfloat16 g_wil[D_ * D_];
__device__ __nv_bfloat16 g_wgh[D_ * D_];
__device__ __nv_bfloat16 g_wgl[D_ * D_];

// ---------------- helpers ----------------
__device__ __forceinline__ uint32_t smem_u32(const void* p) {
    uint32_t a;
    asm("{ .reg .u64 t; cvta.to.shared.u64 t, %1; cvt.u32.u64 %0, t; }" : "=r"(a) : "l"(p));
    return a;
}
__device__ __forceinline__ void cp16(uint32_t dst, const void* src) {
    asm volatile("cp.async.cg.shared.global [%0], [%1], 16;" :: "r"(dst), "l"(src));
}
#define CP_COMMIT() asm volatile("cp.async.commit_group;" ::: "memory")
#define CP_WAIT(n)  asm volatile("cp.async.wait_group %0;" :: "n"(n) : "memory")

__device__ __forceinline__ void ldsm4(uint32_t addr, uint32_t& r0, uint32_t& r1,
                                      uint32_t& r2, uint32_t& r3) {
    asm volatile("ldmatrix.sync.aligned.m8n8.x4.shared.b16 {%0,%1,%2,%3}, [%4];"
                 : "=r"(r0), "=r"(r1), "=r"(r2), "=r"(r3) : "r"(addr));
}
__device__ __forceinline__ void mma16816(float* d, const uint32_t* a, const uint32_t* b) {
    asm volatile("mma.sync.aligned.m16n8k16.row.col.f32.bf16.bf16.f32 "
                 "{%0,%1,%2,%3}, {%4,%5,%6,%7}, {%8,%9}, {%0,%1,%2,%3};"
                 : "+f"(d[0]), "+f"(d[1]), "+f"(d[2]), "+f"(d[3])
                 : "r"(a[0]), "r"(a[1]), "r"(a[2]), "r"(a[3]), "r"(b[0]), "r"(b[1]));
}
__device__ __forceinline__ float sigm(float v) { return 1.0f / (1.0f + __expf(-v)); }

// SW64 swizzle for 64B rows: chunk c (16B) at row r -> c ^ ((r>>1)&3)
__device__ __forceinline__ uint32_t sw64_off(int r, int c) {
    return (uint32_t)(r * 64 + ((c ^ ((r >> 1) & 3)) << 4));
}

// ---------------- fp32 -> bf16 hi/lo split ----------------
__device__ __forceinline__ void split1(float v, unsigned short& h, unsigned short& l) {
    __nv_bfloat16 hb = __float2bfloat16(v);
    float r = v - __bfloat162float(hb);
    __nv_bfloat16 lb = __float2bfloat16(r);
    h = __bfloat16_as_ushort(hb);
    l = __bfloat16_as_ushort(lb);
}

__global__ void __launch_bounds__(256)
conv_x(const float* __restrict__ x)
{
    size_t i = (size_t)blockIdx.x * 256 + threadIdx.x;   // float4 index
    float4 v = ((const float4*)x)[i];
    ushort4 h, l;
    split1(v.x, h.x, l.x); split1(v.y, h.y, l.y);
    split1(v.z, h.z, l.z); split1(v.w, h.w, l.w);
    ((ushort4*)g_xhi)[i] = h;
    ((ushort4*)g_xlo)[i] = l;
}

__global__ void __launch_bounds__(256)
conv_w(const float* __restrict__ wi, const float* __restrict__ wg)
{
    size_t i = (size_t)blockIdx.x * 256 + threadIdx.x;
    float4 a = ((const float4*)wi)[i];
    float4 b = ((const float4*)wg)[i];
    ushort4 h, l;
    split1(a.x, h.x, l.x); split1(a.y, h.y, l.y);
    split1(a.z, h.z, l.z); split1(a.w, h.w, l.w);
    ((ushort4*)g_wih)[i] = h; ((ushort4*)g_wil)[i] = l;
    split1(b.x, h.x, l.x); split1(b.y, h.y, l.y);
    split1(b.z, h.z, l.z); split1(b.w, h.w, l.w);
    ((ushort4*)g_wgh)[i] = h; ((ushort4*)g_wgl)[i] = l;
}

// ---------------- stage loader: gmem -> SW64-swizzled smem ----------------
__device__ __forceinline__ void ld_stage(uint32_t sbase, int kt, int m0, int n0, int tid)
{
    const int k0 = kt * BK;
#pragma unroll
    for (int i = 0; i < 2; i++) {            // x tiles: 128 rows x 4 chunks
        int q = tid + i * 256;
        int r = q >> 2, c = q & 3;
        uint32_t off = sw64_off(r, c);
        size_t gi = (size_t)(m0 + r) * D_ + k0 + c * 8;
        cp16(sbase + OFF_XH + off, g_xhi + gi);
        cp16(sbase + OFF_XL + off, g_xlo + gi);
    }
    {                                        // W tiles: 64 rows x 4 chunks
        int q = tid;
        int r = q >> 2, c = q & 3;
        uint32_t off = sw64_off(r, c);
        size_t gi = (size_t)(n0 + r) * D_ + k0 + c * 8;
        cp16(sbase + OFF_WIH + off, g_wih + gi);
        cp16(sbase + OFF_WIL + off, g_wil + gi);
        cp16(sbase + OFF_WGH + off, g_wgh + gi);
        cp16(sbase + OFF_WGL + off, g_wgl + gi);
    }
}

// ---------------- fused dual-GEMM (HMMA bf16x3) + gate epilogue ----------------
__global__ void __launch_bounds__(256, 2)
gates_gemm_hmma(const float* __restrict__ x,
                const float* __restrict__ bin, const float* __restrict__ bgt,
                const float* __restrict__ lam)
{
    extern __shared__ char smem_raw[];
    char* smem = (char*)(((uintptr_t)smem_raw + 1023) & ~(uintptr_t)1023);
    const uint32_t sb = smem_u32(smem);
    const int tid = threadIdx.x;
    const int lane = tid & 31;
    const int wid = tid >> 5;
    const int wm = wid >> 1;                 // 0..3
    const int wn = wid & 1;                  // 0..1
    const int m0 = blockIdx.y * BM;
    const int n0 = blockIdx.x * BN;

    float* cl_s = (float*)(smem + PAR_OFF);
    float* bi_s = cl_s + 64;
    float* bg_s = bi_s + 64;
    if (tid < 64) {
        float l = lam[n0 + tid];
        cl_s[tid] = 8.0f * log1pf(expf(l));  // C * softplus(lambda)
        bi_s[tid] = bin[n0 + tid];
        bg_s[tid] = bgt[n0 + tid];
    }

    float aig[2][4][4], arg[2][4][4];
#pragma unroll
    for (int mb = 0; mb < 2; mb++)
#pragma unroll
        for (int nb = 0; nb < 4; nb++)
#pragma unroll
            for (int q = 0; q < 4; q++) { aig[mb][nb][q] = 0.f; arg[mb][nb][q] = 0.f; }

    const int r16 = (lane & 7) | (((lane >> 3) & 1) << 3);  // row within 16
    const int coff = lane >> 4;                             // k-chunk offset 0/1
    int arow[2], brow[2];
#pragma unroll
    for (int mb = 0; mb < 2; mb++) arow[mb] = wm * 32 + mb * 16 + r16;
#pragma unroll
    for (int j = 0; j < 2; j++)    brow[j] = wn * 32 + j * 16 + r16;

    // prologue: fill pipeline
#pragma unroll
    for (int s = 0; s < NSTAGE; s++) { ld_stage(sb + s * STAGE_SZ, s, m0, n0, tid); CP_COMMIT(); }

    for (int kt = 0; kt < KT; kt++) {
        const uint32_t stb = sb + (kt % NSTAGE) * STAGE_SZ;
        CP_WAIT(NSTAGE - 1);
        __syncthreads();

#pragma unroll
        for (int k16 = 0; k16 < 2; k16++) {
            const int chunk = k16 * 2 + coff;
            uint32_t axh[2][4], axl[2][4];
#pragma unroll
            for (int mb = 0; mb < 2; mb++) {
                uint32_t off = sw64_off(arow[mb], chunk);
                ldsm4(stb + OFF_XH + off, axh[mb][0], axh[mb][1], axh[mb][2], axh[mb][3]);
                ldsm4(stb + OFF_XL + off, axl[mb][0], axl[mb][1], axl[mb][2], axl[mb][3]);
            }
            // ---- input gate (term-major: acc dependency distance = 8 MMAs) ----
            {
                uint32_t bh[4][2], bl[4][2];
#pragma unroll
                for (int j = 0; j < 2; j++) {
                    uint32_t off = sw64_off(brow[j], chunk);
                    uint32_t r0, r1, r2, r3;
                    ldsm4(stb + OFF_WIH + off, r0, r1, r2, r3);
                    bh[j * 2 + 0][0] = r0; bh[j * 2 + 0][1] = r2;
                    bh[j * 2 + 1][0] = r1; bh[j * 2 + 1][1] = r3;
                    ldsm4(stb + OFF_WIL + off, r0, r1, r2, r3);
                    bl[j * 2 + 0][0] = r0; bl[j * 2 + 0][1] = r2;
                    bl[j * 2 + 1][0] = r1; bl[j * 2 + 1][1] = r3;
                }
#pragma unroll
                for (int mb = 0; mb < 2; mb++)
#pragma unroll
                    for (int nb = 0; nb < 4; nb++)
                        mma16816(aig[mb][nb], axh[mb], bh[nb]);
#pragma unroll
                for (int mb = 0; mb < 2; mb++)
#pragma unroll
                    for (int nb = 0; nb < 4; nb++)
                        mma16816(aig[mb][nb], axl[mb], bh[nb]);
#pragma unroll
                for (int mb = 0; mb < 2; mb++)
#pragma unroll
                    for (int nb = 0; nb < 4; nb++)
                        mma16816(aig[mb][nb], axh[mb], bl[nb]);
            }
            // ---- recurrence gate (term-major) ----
            {
                uint32_t bh[4][2], bl[4][2];
#pragma unroll
                for (int j = 0; j < 2; j++) {
                    uint32_t off = sw64_off(brow[j], chunk);
                    uint32_t r0, r1, r2, r3;
                    ldsm4(stb + OFF_WGH + off, r0, r1, r2, r3);
                    bh[j * 2 + 0][0] = r0; bh[j * 2 + 0][1] = r2;
                    bh[j * 2 + 1][0] = r1; bh[j * 2 + 1][1] = r3;
                    ldsm4(stb + OFF_WGL + off, r0, r1, r2, r3);
                    bl[j * 2 + 0][0] = r0; bl[j * 2 + 0][1] = r2;
                    bl[j * 2 + 1][0] = r1; bl[j * 2 + 1][1] = r3;
                }
#pragma unroll
                for (int mb = 0; mb < 2; mb++)
#pragma unroll
                    for (int nb = 0; nb < 4; nb++)
                        mma16816(arg[mb][nb], axh[mb], bh[nb]);
#pragma unroll
                for (int mb = 0; mb < 2; mb++)
#pragma unroll
                    for (int nb = 0; nb < 4; nb++)
                        mma16816(arg[mb][nb], axl[mb], bh[nb]);
#pragma unroll
                for (int mb = 0; mb < 2; mb++)
#pragma unroll
                    for (int nb = 0; nb < 4; nb++)
                        mma16816(arg[mb][nb], axh[mb], bl[nb]);
            }
        }
        __syncthreads();
        // Always commit a group (possibly empty) so wait_group(NSTAGE-1)
        // always guarantees the consumed stage has landed.
        const int nk = kt + NSTAGE;
        if (nk < KT) ld_stage(stb, nk, m0, n0, tid);
        CP_COMMIT();
    }

    // ---------------- epilogue: gate math + store alpha/xbeta ----------------
    const int g = lane >> 2;
    const int t2 = 2 * (lane & 3);
#pragma unroll
    for (int mb = 0; mb < 2; mb++) {
#pragma unroll
        for (int half = 0; half < 2; half++) {
            const int row = m0 + wm * 32 + mb * 16 + g + half * 8;
#pragma unroll
            for (int nb = 0; nb < 4; nb++) {
                const int cloc = wn * 32 + nb * 8 + t2;
                const size_t gi = (size_t)row * D_ + n0 + cloc;
                float2 xv = *(const float2*)(x + gi);
                float a2[2], v2[2];
#pragma unroll
                for (int q = 0; q < 2; q++) {
                    float ig = aig[mb][nb][half * 2 + q] + bi_s[cloc + q];
                    float rg = arg[mb][nb][half * 2 + q] + bg_s[cloc + q];
                    float sr = sigm(rg);
                    float al = __expf(-cl_s[cloc + q] * sr);
                    float be = sqrtf(fmaxf(1.0f - al * al + 1e-6f, 0.0f));
                    a2[q] = al;
                    v2[q] = be * sigm(ig) * ((q == 0) ? xv.x : xv.y);
                }
                *(float2*)(g_alpha + gi) = make_float2(a2[0], a2[1]);
                *(float2*)(g_xbeta + gi) = make_float2(v2[0], v2[1]);
            }
        }
    }
}

// ---------------- scan kernels (float4, NCHUNK=128 -> 512 blocks) ----------------
__global__ void __launch_bounds__(256)
scan_chunks()
{
    const int gid = blockIdx.x * 256 + threadIdx.x;   // 0 .. 131071
    const int chunk = gid >> 10;                      // / (NCH/4)
    const int c4 = gid & 1023;
    const int b = c4 >> 8;
    const int d = (c4 & 255) * 4;

    size_t fi = (((size_t)b * T_ + (size_t)chunk * TC) * D_ + d) >> 2;  // float4 idx
    float4 A = make_float4(1.f, 1.f, 1.f, 1.f);
    float4 Bv = make_float4(0.f, 0.f, 0.f, 0.f);
#pragma unroll 4
    for (int t = 0; t < TC; t++) {
        float4 a = ((const float4*)g_alpha)[fi];
        float4 v = ((const float4*)g_xbeta)[fi];
        Bv.x = fmaf(a.x, Bv.x, v.x); A.x *= a.x;
        Bv.y = fmaf(a.y, Bv.y, v.y); A.y *= a.y;
        Bv.z = fmaf(a.z, Bv.z, v.z); A.z *= a.z;
        Bv.w = fmaf(a.w, Bv.w, v.w); A.w *= a.w;
        fi += D_ / 4;
    }
    const size_t ch4 = ((size_t)chunk * NCH + b * D_ + d) >> 2;
    ((float4*)g_Ac)[ch4] = A;
    ((float4*)g_Bc)[ch4] = Bv;
}

__global__ void __launch_bounds__(256)
scan_carry()
{
    const int c4 = blockIdx.x * 256 + threadIdx.x;    // 0..1023 (NCH/4)
    float4 h = make_float4(0.f, 0.f, 0.f, 0.f);
#pragma unroll 4
    for (int c = 0; c < NCHUNK; c++) {
        const size_t i = ((size_t)c * NCH) / 4 + c4;
        ((float4*)g_carry)[i] = h;
        float4 a = ((const float4*)g_Ac)[i];
        float4 v = ((const float4*)g_Bc)[i];
        h.x = fmaf(a.x, h.x, v.x);
        h.y = fmaf(a.y, h.y, v.y);
        h.z = fmaf(a.z, h.z, v.z);
        h.w = fmaf(a.w, h.w, v.w);
    }
}

__global__ void __launch_bounds__(256)
scan_apply(float* __restrict__ out)
{
    const int gid = blockIdx.x * 256 + threadIdx.x;
    const int chunk = gid >> 10;
    const int c4 = gid & 1023;
    const int b = c4 >> 8;
    const int d = (c4 & 255) * 4;

    size_t fi = (((size_t)b * T_ + (size_t)chunk * TC) * D_ + d) >> 2;
    float4 h = ((const float4*)g_carry)[((size_t)chunk * NCH + b * D_ + d) >> 2];
#pragma unroll 4
    for (int t = 0; t < TC; t++) {
        float4 a = ((const float4*)g_alpha)[fi];
        float4 v = ((const float4*)g_xbeta)[fi];
        h.x = fmaf(a.x, h.x, v.x);
        h.y = fmaf(a.y, h.y, v.y);
        h.z = fmaf(a.z, h.z, v.z);
        h.w = fmaf(a.w, h.w, v.w);
        ((float4*)out)[fi] = h;
        fi += D_ / 4;
    }
}

// ---------------- launch ----------------
extern "C" void kernel_launch(void* const* d_in, const int* in_sizes, int n_in,
                              void* d_out, int out_size)
{
    const float* x   = (const float*)d_in[0];
    const float* Win = (const float*)d_in[1];
    const float* bin = (const float*)d_in[2];
    const float* Wg  = (const float*)d_in[3];
    const float* bgt = (const float*)d_in[4];
    const float* lam = (const float*)d_in[5];
    float* out = (float*)d_out;

    cudaFuncSetAttribute(gates_gemm_hmma, cudaFuncAttributeMaxDynamicSharedMemorySize, SMEM_DYN);

    conv_x<<<(M_ * (D_ / 4)) / 256, 256>>>(x);
    conv_w<<<(D_ * (D_ / 4)) / 256, 256>>>(Win, Wg);

    dim3 ggrid(D_ / BN, M_ / BM);                // (16, 256)
    gates_gemm_hmma<<<ggrid, 256, SMEM_DYN>>>(x, bin, bgt, lam);

    scan_chunks<<<(NCHUNK * (NCH / 4)) / 256, 256>>>();   // 512 blocks
    scan_carry<<<(NCH / 4) / 256, 256>>>();               // 4 blocks
    scan_apply<<<(NCHUNK * (NCH / 4)) / 256, 256>>>(out); // 512 blocks
}

// round 6
// speedup vs baseline: 4.6886x; 1.8928x over previous
#include <cuda_runtime.h>
#include <cuda_fp16.h>
#include <math.h>
#include <stdint.h>

// Problem constants (RG_LRU: B=4, T=8192, D=1024, C=8)
#define B_ 4
#define T_ 8192
#define D_ 1024
#define M_ (B_ * T_)          // 32768 rows

// Scan chunking
#define NCHUNK 128
#define TC (T_ / NCHUNK)      // 64
#define NCH (B_ * D_)         // 4096 channels

// GEMM tiling
#define BM 128
#define BN 64
#define BK 32                 // fp16 per K-tile = 64 B rows (SW64 atom)
#define KT (D_ / BK)          // 32

// smem stage layout (bytes): x tile 128x64B = 8KB, W tiles 64x64B = 4KB each
#define OFF_X   0
#define OFF_WI  8192
#define OFF_WG  12288
#define STAGE_SZ 16384
#define NSTAGE 4
#define PAR_OFF (NSTAGE * STAGE_SZ)          // gate params: 3 x 64 floats
#define SMEM_DYN (PAR_OFF + 1024 + 1024)     // ~66 KB -> 2 CTAs/SM

// ---------------- device scratch (allocation-free) ----------------
__device__ float g_alpha[(size_t)M_ * D_];   // 128 MB
__device__ float g_xbeta[(size_t)M_ * D_];   // 128 MB
__device__ float g_Ac[NCHUNK * NCH];
__device__ float g_Bc[NCHUNK * NCH];
__device__ float g_carry[NCHUNK * NCH];
__device__ __half g_xh[(size_t)M_ * D_];     // 64 MB
__device__ __half g_wi[D_ * D_];             // 2 MB
__device__ __half g_wg[D_ * D_];             // 2 MB

// ---------------- helpers ----------------
__device__ __forceinline__ uint32_t smem_u32(const void* p) {
    uint32_t a;
    asm("{ .reg .u64 t; cvta.to.shared.u64 t, %1; cvt.u32.u64 %0, t; }" : "=r"(a) : "l"(p));
    return a;
}
__device__ __forceinline__ void cp16(uint32_t dst, const void* src) {
    asm volatile("cp.async.cg.shared.global [%0], [%1], 16;" :: "r"(dst), "l"(src));
}
#define CP_COMMIT() asm volatile("cp.async.commit_group;" ::: "memory")
#define CP_WAIT(n)  asm volatile("cp.async.wait_group %0;" :: "n"(n) : "memory")

__device__ __forceinline__ void ldsm4(uint32_t addr, uint32_t& r0, uint32_t& r1,
                                      uint32_t& r2, uint32_t& r3) {
    asm volatile("ldmatrix.sync.aligned.m8n8.x4.shared.b16 {%0,%1,%2,%3}, [%4];"
                 : "=r"(r0), "=r"(r1), "=r"(r2), "=r"(r3) : "r"(addr));
}
__device__ __forceinline__ void mma16816(float* d, const uint32_t* a, const uint32_t* b) {
    asm volatile("mma.sync.aligned.m16n8k16.row.col.f32.f16.f16.f32 "
                 "{%0,%1,%2,%3}, {%4,%5,%6,%7}, {%8,%9}, {%0,%1,%2,%3};"
                 : "+f"(d[0]), "+f"(d[1]), "+f"(d[2]), "+f"(d[3])
                 : "r"(a[0]), "r"(a[1]), "r"(a[2]), "r"(a[3]), "r"(b[0]), "r"(b[1]));
}
__device__ __forceinline__ float sigm(float v) { return 1.0f / (1.0f + __expf(-v)); }

// SW64 swizzle for 64B rows: chunk c (16B) at row r -> c ^ ((r>>1)&3)
__device__ __forceinline__ uint32_t sw64_off(int r, int c) {
    return (uint32_t)(r * 64 + ((c ^ ((r >> 1) & 3)) << 4));
}

// ---------------- fp32 -> fp16 conversion kernels ----------------
__global__ void __launch_bounds__(256)
conv_x(const float* __restrict__ x)
{
    size_t i = (size_t)blockIdx.x * 256 + threadIdx.x;   // float4 index
    float4 v = ((const float4*)x)[i];
    ushort4 h;
    h.x = __half_as_ushort(__float2half(v.x));
    h.y = __half_as_ushort(__float2half(v.y));
    h.z = __half_as_ushort(__float2half(v.z));
    h.w = __half_as_ushort(__float2half(v.w));
    ((ushort4*)g_xh)[i] = h;
}

__global__ void __launch_bounds__(256)
conv_w(const float* __restrict__ wi, const float* __restrict__ wg)
{
    size_t i = (size_t)blockIdx.x * 256 + threadIdx.x;
    float4 a = ((const float4*)wi)[i];
    float4 b = ((const float4*)wg)[i];
    ushort4 h;
    h.x = __half_as_ushort(__float2half(a.x));
    h.y = __half_as_ushort(__float2half(a.y));
    h.z = __half_as_ushort(__float2half(a.z));
    h.w = __half_as_ushort(__float2half(a.w));
    ((ushort4*)g_wi)[i] = h;
    h.x = __half_as_ushort(__float2half(b.x));
    h.y = __half_as_ushort(__float2half(b.y));
    h.z = __half_as_ushort(__float2half(b.z));
    h.w = __half_as_ushort(__float2half(b.w));
    ((ushort4*)g_wg)[i] = h;
}

// ---------------- stage loader: gmem -> SW64-swizzled smem ----------------
__device__ __forceinline__ void ld_stage(uint32_t sbase, int kt, int m0, int n0, int tid)
{
    const int k0 = kt * BK;
#pragma unroll
    for (int i = 0; i < 2; i++) {            // x tile: 128 rows x 4 chunks
        int q = tid + i * 256;
        int r = q >> 2, c = q & 3;
        uint32_t off = sw64_off(r, c);
        size_t gi = (size_t)(m0 + r) * D_ + k0 + c * 8;
        cp16(sbase + OFF_X + off, g_xh + gi);
    }
    {                                        // W tiles: 64 rows x 4 chunks
        int q = tid;
        int r = q >> 2, c = q & 3;
        uint32_t off = sw64_off(r, c);
        size_t gi = (size_t)(n0 + r) * D_ + k0 + c * 8;
        cp16(sbase + OFF_WI + off, g_wi + gi);
        cp16(sbase + OFF_WG + off, g_wg + gi);
    }
}

// ---------------- fused dual-GEMM (HMMA fp16) + gate epilogue ----------------
__global__ void __launch_bounds__(256, 2)
gates_gemm_hmma(const float* __restrict__ x,
                const float* __restrict__ bin, const float* __restrict__ bgt,
                const float* __restrict__ lam)
{
    extern __shared__ char smem_raw[];
    char* smem = (char*)(((uintptr_t)smem_raw + 1023) & ~(uintptr_t)1023);
    const uint32_t sb = smem_u32(smem);
    const int tid = threadIdx.x;
    const int lane = tid & 31;
    const int wid = tid >> 5;
    const int wm = wid >> 1;                 // 0..3
    const int wn = wid & 1;                  // 0..1
    const int m0 = blockIdx.y * BM;
    const int n0 = blockIdx.x * BN;

    float* cl_s = (float*)(smem + PAR_OFF);
    float* bi_s = cl_s + 64;
    float* bg_s = bi_s + 64;
    if (tid < 64) {
        float l = lam[n0 + tid];
        cl_s[tid] = 8.0f * log1pf(expf(l));  // C * softplus(lambda)
        bi_s[tid] = bin[n0 + tid];
        bg_s[tid] = bgt[n0 + tid];
    }

    float aig[2][4][4], arg[2][4][4];
#pragma unroll
    for (int mb = 0; mb < 2; mb++)
#pragma unroll
        for (int nb = 0; nb < 4; nb++)
#pragma unroll
            for (int q = 0; q < 4; q++) { aig[mb][nb][q] = 0.f; arg[mb][nb][q] = 0.f; }

    const int r16 = (lane & 7) | (((lane >> 3) & 1) << 3);  // row within 16
    const int coff = lane >> 4;                             // k-chunk offset 0/1
    int arow[2], brow[2];
#pragma unroll
    for (int mb = 0; mb < 2; mb++) arow[mb] = wm * 32 + mb * 16 + r16;
#pragma unroll
    for (int j = 0; j < 2; j++)    brow[j] = wn * 32 + j * 16 + r16;

    // prologue: fill pipeline
#pragma unroll
    for (int s = 0; s < NSTAGE; s++) { ld_stage(sb + s * STAGE_SZ, s, m0, n0, tid); CP_COMMIT(); }

    for (int kt = 0; kt < KT; kt++) {
        const uint32_t stb = sb + (kt % NSTAGE) * STAGE_SZ;
        CP_WAIT(NSTAGE - 1);
        __syncthreads();

#pragma unroll
        for (int k16 = 0; k16 < 2; k16++) {
            const int chunk = k16 * 2 + coff;
            uint32_t ax[2][4];
#pragma unroll
            for (int mb = 0; mb < 2; mb++) {
                uint32_t off = sw64_off(arow[mb], chunk);
                ldsm4(stb + OFF_X + off, ax[mb][0], ax[mb][1], ax[mb][2], ax[mb][3]);
            }
            uint32_t bwi[4][2], bwg[4][2];
#pragma unroll
            for (int j = 0; j < 2; j++) {
                uint32_t off = sw64_off(brow[j], chunk);
                uint32_t r0, r1, r2, r3;
                ldsm4(stb + OFF_WI + off, r0, r1, r2, r3);
                bwi[j * 2 + 0][0] = r0; bwi[j * 2 + 0][1] = r2;
                bwi[j * 2 + 1][0] = r1; bwi[j * 2 + 1][1] = r3;
                ldsm4(stb + OFF_WG + off, r0, r1, r2, r3);
                bwg[j * 2 + 0][0] = r0; bwg[j * 2 + 0][1] = r2;
                bwg[j * 2 + 1][0] = r1; bwg[j * 2 + 1][1] = r3;
            }
#pragma unroll
            for (int mb = 0; mb < 2; mb++)
#pragma unroll
                for (int nb = 0; nb < 4; nb++)
                    mma16816(aig[mb][nb], ax[mb], bwi[nb]);
#pragma unroll
            for (int mb = 0; mb < 2; mb++)
#pragma unroll
                for (int nb = 0; nb < 4; nb++)
                    mma16816(arg[mb][nb], ax[mb], bwg[nb]);
        }
        __syncthreads();
        // Always commit a group (possibly empty) so wait_group(NSTAGE-1)
        // always guarantees the consumed stage has landed.
        const int nk = kt + NSTAGE;
        if (nk < KT) ld_stage(stb, nk, m0, n0, tid);
        CP_COMMIT();
    }

    // ---------------- epilogue: gate math + store alpha/xbeta ----------------
    const int g = lane >> 2;
    const int t2 = 2 * (lane & 3);
#pragma unroll
    for (int mb = 0; mb < 2; mb++) {
#pragma unroll
        for (int half = 0; half < 2; half++) {
            const int row = m0 + wm * 32 + mb * 16 + g + half * 8;
#pragma unroll
            for (int nb = 0; nb < 4; nb++) {
                const int cloc = wn * 32 + nb * 8 + t2;
                const size_t gi = (size_t)row * D_ + n0 + cloc;
                float2 xv = *(const float2*)(x + gi);
                float a2[2], v2[2];
#pragma unroll
                for (int q = 0; q < 2; q++) {
                    float ig = aig[mb][nb][half * 2 + q] + bi_s[cloc + q];
                    float rg = arg[mb][nb][half * 2 + q] + bg_s[cloc + q];
                    float sr = sigm(rg);
                    float al = __expf(-cl_s[cloc + q] * sr);
                    float be = sqrtf(fmaxf(1.0f - al * al + 1e-6f, 0.0f));
                    a2[q] = al;
                    v2[q] = be * sigm(ig) * ((q == 0) ? xv.x : xv.y);
                }
                *(float2*)(g_alpha + gi) = make_float2(a2[0], a2[1]);
                *(float2*)(g_xbeta + gi) = make_float2(v2[0], v2[1]);
            }
        }
    }
}

// ---------------- scan kernels (float4, NCHUNK=128 -> 512 blocks) ----------------
__global__ void __launch_bounds__(256)
scan_chunks()
{
    const int gid = blockIdx.x * 256 + threadIdx.x;   // 0 .. 131071
    const int chunk = gid >> 10;                      // / (NCH/4)
    const int c4 = gid & 1023;
    const int b = c4 >> 8;
    const int d = (c4 & 255) * 4;

    size_t fi = (((size_t)b * T_ + (size_t)chunk * TC) * D_ + d) >> 2;  // float4 idx
    float4 A = make_float4(1.f, 1.f, 1.f, 1.f);
    float4 Bv = make_float4(0.f, 0.f, 0.f, 0.f);
#pragma unroll 4
    for (int t = 0; t < TC; t++) {
        float4 a = ((const float4*)g_alpha)[fi];
        float4 v = ((const float4*)g_xbeta)[fi];
        Bv.x = fmaf(a.x, Bv.x, v.x); A.x *= a.x;
        Bv.y = fmaf(a.y, Bv.y, v.y); A.y *= a.y;
        Bv.z = fmaf(a.z, Bv.z, v.z); A.z *= a.z;
        Bv.w = fmaf(a.w, Bv.w, v.w); A.w *= a.w;
        fi += D_ / 4;
    }
    const size_t ch4 = ((size_t)chunk * NCH + b * D_ + d) >> 2;
    ((float4*)g_Ac)[ch4] = A;
    ((float4*)g_Bc)[ch4] = Bv;
}

__global__ void __launch_bounds__(256)
scan_carry()
{
    const int c4 = blockIdx.x * 256 + threadIdx.x;    // 0..1023 (NCH/4)
    float4 h = make_float4(0.f, 0.f, 0.f, 0.f);
#pragma unroll 4
    for (int c = 0; c < NCHUNK; c++) {
        const size_t i = ((size_t)c * NCH) / 4 + c4;
        ((float4*)g_carry)[i] = h;
        float4 a = ((const float4*)g_Ac)[i];
        float4 v = ((const float4*)g_Bc)[i];
        h.x = fmaf(a.x, h.x, v.x);
        h.y = fmaf(a.y, h.y, v.y);
        h.z = fmaf(a.z, h.z, v.z);
        h.w = fmaf(a.w, h.w, v.w);
    }
}

__global__ void __launch_bounds__(256)
scan_apply(float* __restrict__ out)
{
    const int gid = blockIdx.x * 256 + threadIdx.x;
    const int chunk = gid >> 10;
    const int c4 = gid & 1023;
    const int b = c4 >> 8;
    const int d = (c4 & 255) * 4;

    size_t fi = (((size_t)b * T_ + (size_t)chunk * TC) * D_ + d) >> 2;
    float4 h = ((const float4*)g_carry)[((size_t)chunk * NCH + b * D_ + d) >> 2];
#pragma unroll 4
    for (int t = 0; t < TC; t++) {
        float4 a = ((const float4*)g_alpha)[fi];
        float4 v = ((const float4*)g_xbeta)[fi];
        h.x = fmaf(a.x, h.x, v.x);
        h.y = fmaf(a.y, h.y, v.y);
        h.z = fmaf(a.z, h.z, v.z);
        h.w = fmaf(a.w, h.w, v.w);
        ((float4*)out)[fi] = h;
        fi += D_ / 4;
    }
}

// ---------------- launch ----------------
extern "C" void kernel_launch(void* const* d_in, const int* in_sizes, int n_in,
                              void* d_out, int out_size)
{
    const float* x   = (const float*)d_in[0];
    const float* Win = (const float*)d_in[1];
    const float* bin = (const float*)d_in[2];
    const float* Wg  = (const float*)d_in[3];
    const float* bgt = (const float*)d_in[4];
    const float* lam = (const float*)d_in[5];
    float* out = (float*)d_out;

    cudaFuncSetAttribute(gates_gemm_hmma, cudaFuncAttributeMaxDynamicSharedMemorySize, SMEM_DYN);

    conv_x<<<(M_ * (D_ / 4)) / 256, 256>>>(x);
    conv_w<<<(D_ * (D_ / 4)) / 256, 256>>>(Win, Wg);

    dim3 ggrid(D_ / BN, M_ / BM);                // (16, 256)
    gates_gemm_hmma<<<ggrid, 256, SMEM_DYN>>>(x, bin, bgt, lam);

    scan_chunks<<<(NCHUNK * (NCH / 4)) / 256, 256>>>();   // 512 blocks
    scan_carry<<<(NCH / 4) / 256, 256>>>();               // 4 blocks
    scan_apply<<<(NCHUNK * (NCH / 4)) / 256, 256>>>(out); // 512 blocks
}

// round 7
// speedup vs baseline: 4.9529x; 1.0564x over previous
#include <cuda_runtime.h>
#include <cuda_fp16.h>
#include <math.h>
#include <stdint.h>

// Problem constants (RG_LRU: B=4, T=8192, D=1024, C=8)
#define B_ 4
#define T_ 8192
#define D_ 1024
#define M_ (B_ * T_)          // 32768 rows

// Chunked scan: chunk == GEMM row tile (128 consecutive timesteps)
#define TCHUNK 128
#define NCHK_PER_B (T_ / TCHUNK)      // 64
#define NCHUNKS (M_ / TCHUNK)         // 256

// GEMM tiling
#define BM 128
#define BN 64
#define BK 32                 // fp16 per K-tile = 64 B rows (SW64 atom)
#define KT (D_ / BK)          // 32

// smem stage layout (bytes): x tile 128x64B = 8KB, W tiles 64x64B = 4KB each
#define OFF_X   0
#define OFF_WI  8192
#define OFF_WG  12288
#define STAGE_SZ 16384
#define NSTAGE 5              // 80 KB pipeline

// epilogue scan arrays (union with pipeline stages)
#define AL_STRIDE 66                     // padded row stride (floats)
#define AL_OFF  0                        // alpha  [128][66] = 33792 B
#define XB_OFF  33792                    // xbeta  [128][66] = 33792 B
#define AGG_OFF 67584                    // seg aggregates: 2 x 256 floats = 2 KB
// params live beyond both regions
#define PAR_OFF (NSTAGE * STAGE_SZ)      // 81920
#define SMEM_DYN (PAR_OFF + 768 + 1024)  // ~83.6 KB -> 2 CTAs/SM

// ---------------- device scratch (allocation-free) ----------------
// After the fused epilogue these hold PREFIX pairs: h_t = P_t * carry + S_t
__device__ float g_P[(size_t)M_ * D_];       // 128 MB (prefix products)
__device__ float g_S[(size_t)M_ * D_];       // 128 MB (prefix scan values)
__device__ float g_Ac[(size_t)NCHUNKS * D_]; // chunk aggregate products
__device__ float g_Bc[(size_t)NCHUNKS * D_]; // chunk aggregate scan values
__device__ float g_carry[(size_t)NCHUNKS * D_];
__device__ __half g_xh[(size_t)M_ * D_];     // 64 MB
__device__ __half g_wi[D_ * D_];             // 2 MB
__device__ __half g_wg[D_ * D_];             // 2 MB

// ---------------- helpers ----------------
__device__ __forceinline__ uint32_t smem_u32(const void* p) {
    uint32_t a;
    asm("{ .reg .u64 t; cvta.to.shared.u64 t, %1; cvt.u32.u64 %0, t; }" : "=r"(a) : "l"(p));
    return a;
}
__device__ __forceinline__ void cp16(uint32_t dst, const void* src) {
    asm volatile("cp.async.cg.shared.global [%0], [%1], 16;" :: "r"(dst), "l"(src));
}
#define CP_COMMIT() asm volatile("cp.async.commit_group;" ::: "memory")
#define CP_WAIT(n)  asm volatile("cp.async.wait_group %0;" :: "n"(n) : "memory")

__device__ __forceinline__ void ldsm4(uint32_t addr, uint32_t& r0, uint32_t& r1,
                                      uint32_t& r2, uint32_t& r3) {
    asm volatile("ldmatrix.sync.aligned.m8n8.x4.shared.b16 {%0,%1,%2,%3}, [%4];"
                 : "=r"(r0), "=r"(r1), "=r"(r2), "=r"(r3) : "r"(addr));
}
__device__ __forceinline__ void mma16816(float* d, const uint32_t* a, const uint32_t* b) {
    asm volatile("mma.sync.aligned.m16n8k16.row.col.f32.f16.f16.f32 "
                 "{%0,%1,%2,%3}, {%4,%5,%6,%7}, {%8,%9}, {%0,%1,%2,%3};"
                 : "+f"(d[0]), "+f"(d[1]), "+f"(d[2]), "+f"(d[3])
                 : "r"(a[0]), "r"(a[1]), "r"(a[2]), "r"(a[3]), "r"(b[0]), "r"(b[1]));
}
__device__ __forceinline__ float sigm(float v) { return 1.0f / (1.0f + __expf(-v)); }

// SW64 swizzle for 64B rows: chunk c (16B) at row r -> c ^ ((r>>1)&3)
__device__ __forceinline__ uint32_t sw64_off(int r, int c) {
    return (uint32_t)(r * 64 + ((c ^ ((r >> 1) & 3)) << 4));
}

// ---------------- fp32 -> fp16 conversion kernels ----------------
__global__ void __launch_bounds__(256)
conv_x(const float* __restrict__ x)
{
    size_t i = (size_t)blockIdx.x * 256 + threadIdx.x;   // float4 index
    float4 v = ((const float4*)x)[i];
    ushort4 h;
    h.x = __half_as_ushort(__float2half(v.x));
    h.y = __half_as_ushort(__float2half(v.y));
    h.z = __half_as_ushort(__float2half(v.z));
    h.w = __half_as_ushort(__float2half(v.w));
    ((ushort4*)g_xh)[i] = h;
}

__global__ void __launch_bounds__(256)
conv_w(const float* __restrict__ wi, const float* __restrict__ wg)
{
    size_t i = (size_t)blockIdx.x * 256 + threadIdx.x;
    float4 a = ((const float4*)wi)[i];
    float4 b = ((const float4*)wg)[i];
    ushort4 h;
    h.x = __half_as_ushort(__float2half(a.x));
    h.y = __half_as_ushort(__float2half(a.y));
    h.z = __half_as_ushort(__float2half(a.z));
    h.w = __half_as_ushort(__float2half(a.w));
    ((ushort4*)g_wi)[i] = h;
    h.x = __half_as_ushort(__float2half(b.x));
    h.y = __half_as_ushort(__float2half(b.y));
    h.z = __half_as_ushort(__float2half(b.z));
    h.w = __half_as_ushort(__float2half(b.w));
    ((ushort4*)g_wg)[i] = h;
}

// ---------------- stage loader: gmem -> SW64-swizzled smem ----------------
__device__ __forceinline__ void ld_stage(uint32_t sbase, int kt, int m0, int n0, int tid)
{
    const int k0 = kt * BK;
#pragma unroll
    for (int i = 0; i < 2; i++) {            // x tile: 128 rows x 4 chunks
        int q = tid + i * 256;
        int r = q >> 2, c = q & 3;
        uint32_t off = sw64_off(r, c);
        size_t gi = (size_t)(m0 + r) * D_ + k0 + c * 8;
        cp16(sbase + OFF_X + off, g_xh + gi);
    }
    {                                        // W tiles: 64 rows x 4 chunks
        int q = tid;
        int r = q >> 2, c = q & 3;
        uint32_t off = sw64_off(r, c);
        size_t gi = (size_t)(n0 + r) * D_ + k0 + c * 8;
        cp16(sbase + OFF_WI + off, g_wi + gi);
        cp16(sbase + OFF_WG + off, g_wg + gi);
    }
}

// ---- fused dual-GEMM (HMMA fp16) + gate epilogue + intra-chunk prefix scan ----
__global__ void __launch_bounds__(256, 2)
gates_gemm_hmma(const float* __restrict__ x,
                const float* __restrict__ bin, const float* __restrict__ bgt,
                const float* __restrict__ lam)
{
    extern __shared__ char smem_raw[];
    char* smem = (char*)(((uintptr_t)smem_raw + 1023) & ~(uintptr_t)1023);
    const uint32_t sb = smem_u32(smem);
    const int tid = threadIdx.x;
    const int lane = tid & 31;
    const int wid = tid >> 5;
    const int wm = wid >> 1;                 // 0..3
    const int wn = wid & 1;                  // 0..1
    const int m0 = blockIdx.y * BM;          // chunk start row (within one batch)
    const int n0 = blockIdx.x * BN;

    float* cl_s = (float*)(smem + PAR_OFF);
    float* bi_s = cl_s + 64;
    float* bg_s = bi_s + 64;
    if (tid < 64) {
        float l = lam[n0 + tid];
        cl_s[tid] = 8.0f * log1pf(expf(l));  // C * softplus(lambda)
        bi_s[tid] = bin[n0 + tid];
        bg_s[tid] = bgt[n0 + tid];
    }

    float aig[2][4][4], arg[2][4][4];
#pragma unroll
    for (int mb = 0; mb < 2; mb++)
#pragma unroll
        for (int nb = 0; nb < 4; nb++)
#pragma unroll
            for (int q = 0; q < 4; q++) { aig[mb][nb][q] = 0.f; arg[mb][nb][q] = 0.f; }

    const int r16 = (lane & 7) | (((lane >> 3) & 1) << 3);  // row within 16
    const int coff = lane >> 4;                             // k-chunk offset 0/1
    int arow[2], brow[2];
#pragma unroll
    for (int mb = 0; mb < 2; mb++) arow[mb] = wm * 32 + mb * 16 + r16;
#pragma unroll
    for (int j = 0; j < 2; j++)    brow[j] = wn * 32 + j * 16 + r16;

    // prologue: fill pipeline
#pragma unroll
    for (int s = 0; s < NSTAGE; s++) { ld_stage(sb + s * STAGE_SZ, s, m0, n0, tid); CP_COMMIT(); }

    for (int kt = 0; kt < KT; kt++) {
        const uint32_t stb = sb + (kt % NSTAGE) * STAGE_SZ;
        CP_WAIT(NSTAGE - 1);
        __syncthreads();

#pragma unroll
        for (int k16 = 0; k16 < 2; k16++) {
            const int chunk = k16 * 2 + coff;
            uint32_t ax[2][4];
#pragma unroll
            for (int mb = 0; mb < 2; mb++) {
                uint32_t off = sw64_off(arow[mb], chunk);
                ldsm4(stb + OFF_X + off, ax[mb][0], ax[mb][1], ax[mb][2], ax[mb][3]);
            }
            uint32_t bwi[4][2], bwg[4][2];
#pragma unroll
            for (int j = 0; j < 2; j++) {
                uint32_t off = sw64_off(brow[j], chunk);
                uint32_t r0, r1, r2, r3;
                ldsm4(stb + OFF_WI + off, r0, r1, r2, r3);
                bwi[j * 2 + 0][0] = r0; bwi[j * 2 + 0][1] = r2;
                bwi[j * 2 + 1][0] = r1; bwi[j * 2 + 1][1] = r3;
                ldsm4(stb + OFF_WG + off, r0, r1, r2, r3);
                bwg[j * 2 + 0][0] = r0; bwg[j * 2 + 0][1] = r2;
                bwg[j * 2 + 1][0] = r1; bwg[j * 2 + 1][1] = r3;
            }
#pragma unroll
            for (int mb = 0; mb < 2; mb++)
#pragma unroll
                for (int nb = 0; nb < 4; nb++)
                    mma16816(aig[mb][nb], ax[mb], bwi[nb]);
#pragma unroll
            for (int mb = 0; mb < 2; mb++)
#pragma unroll
                for (int nb = 0; nb < 4; nb++)
                    mma16816(arg[mb][nb], ax[mb], bwg[nb]);
        }
        __syncthreads();
        // Always commit a group (possibly empty) so wait_group(NSTAGE-1)
        // always guarantees the consumed stage has landed.
        const int nk = kt + NSTAGE;
        if (nk < KT) ld_stage(stb, nk, m0, n0, tid);
        CP_COMMIT();
    }

    // -------- epilogue 1: gate math -> smem (reusing dead stage memory) --------
    float* al_s = (float*)(smem + AL_OFF);   // [128][AL_STRIDE]
    float* xb_s = (float*)(smem + XB_OFF);
    const int g = lane >> 2;
    const int t2 = 2 * (lane & 3);
#pragma unroll
    for (int mb = 0; mb < 2; mb++) {
#pragma unroll
        for (int half = 0; half < 2; half++) {
            const int rl = wm * 32 + mb * 16 + g + half * 8;   // 0..127
#pragma unroll
            for (int nb = 0; nb < 4; nb++) {
                const int cloc = wn * 32 + nb * 8 + t2;        // 0..63
                const size_t gi = (size_t)(m0 + rl) * D_ + n0 + cloc;
                float2 xv = *(const float2*)(x + gi);
                float a2[2], v2[2];
#pragma unroll
                for (int q = 0; q < 2; q++) {
                    float ig = aig[mb][nb][half * 2 + q] + bi_s[cloc + q];
                    float rg = arg[mb][nb][half * 2 + q] + bg_s[cloc + q];
                    float sr = sigm(rg);
                    float al = __expf(-cl_s[cloc + q] * sr);
                    float be = sqrtf(fmaxf(1.0f - al * al + 1e-6f, 0.0f));
                    a2[q] = al;
                    v2[q] = be * sigm(ig) * ((q == 0) ? xv.x : xv.y);
                }
                *(float2*)(al_s + rl * AL_STRIDE + cloc) = make_float2(a2[0], a2[1]);
                *(float2*)(xb_s + rl * AL_STRIDE + cloc) = make_float2(v2[0], v2[1]);
            }
        }
    }
    __syncthreads();

    // -------- epilogue 2: intra-chunk prefix scan (h_t = P_t*carry + S_t) --------
    const int seg = tid >> 6;        // 4 segments of 32 timesteps
    const int ch  = tid & 63;        // channel within tile
    float P = 1.f, S = 0.f;
#pragma unroll 8
    for (int s = 0; s < 32; s++) {
        float a = al_s[(seg * 32 + s) * AL_STRIDE + ch];
        float v = xb_s[(seg * 32 + s) * AL_STRIDE + ch];
        S = fmaf(a, S, v);
        P *= a;
    }
    float* aggP = (float*)(smem + AGG_OFF);
    float* aggS = aggP + 256;
    aggP[seg * 64 + ch] = P;
    aggS[seg * 64 + ch] = S;
    __syncthreads();
    float Pc = 1.f, Sc = 0.f;
#pragma unroll
    for (int q = 0; q < 3; q++) {
        if (q < seg) {
            float pq = aggP[q * 64 + ch], sq = aggS[q * 64 + ch];
            Sc = fmaf(pq, Sc, sq);
            Pc *= pq;
        }
    }
    P = Pc; S = Sc;
#pragma unroll 8
    for (int s = 0; s < 32; s++) {
        const int rl = seg * 32 + s;
        float a = al_s[rl * AL_STRIDE + ch];
        float v = xb_s[rl * AL_STRIDE + ch];
        P *= a;
        S = fmaf(a, S, v);
        const size_t gi = (size_t)(m0 + rl) * D_ + n0 + ch;
        g_P[gi] = P;
        g_S[gi] = S;
    }
    if (seg == 3) {
        const size_t ci = (size_t)blockIdx.y * D_ + n0 + ch;
        g_Ac[ci] = P;
        g_Bc[ci] = S;
    }
}

// ---------------- carry scan over chunk aggregates ----------------
__global__ void __launch_bounds__(256)
scan_carry()
{
    const int b = blockIdx.x;                 // 0..3 (batch)
    const int d4 = threadIdx.x;               // 0..255 (float4 channel group)
    float4 h = make_float4(0.f, 0.f, 0.f, 0.f);
#pragma unroll 4
    for (int tc = 0; tc < NCHK_PER_B; tc++) {
        const size_t i = (size_t)(b * NCHK_PER_B + tc) * (D_ / 4) + d4;
        ((float4*)g_carry)[i] = h;
        float4 a = ((const float4*)g_Ac)[i];
        float4 v = ((const float4*)g_Bc)[i];
        h.x = fmaf(a.x, h.x, v.x);
        h.y = fmaf(a.y, h.y, v.y);
        h.z = fmaf(a.z, h.z, v.z);
        h.w = fmaf(a.w, h.w, v.w);
    }
}

// ---------------- elementwise apply: out = P*carry + S ----------------
__global__ void __launch_bounds__(256)
scan_apply(float* __restrict__ out)
{
    const int gid = blockIdx.x * 256 + threadIdx.x;    // 0 .. 262143
    const int cid = gid >> 10;                         // chunk 0..255
    const int seg = (gid >> 8) & 3;                    // 32-step segment
    const int d4  = gid & 255;

    const float4 c = ((const float4*)g_carry)[(size_t)cid * (D_ / 4) + d4];
    size_t fi = (size_t)(cid * TCHUNK + seg * 32) * (D_ / 4) + d4;
#pragma unroll 4
    for (int s = 0; s < 32; s++) {
        float4 P = ((const float4*)g_P)[fi];
        float4 S = ((const float4*)g_S)[fi];
        float4 o;
        o.x = fmaf(P.x, c.x, S.x);
        o.y = fmaf(P.y, c.y, S.y);
        o.z = fmaf(P.z, c.z, S.z);
        o.w = fmaf(P.w, c.w, S.w);
        ((float4*)out)[fi] = o;
        fi += D_ / 4;
    }
}

// ---------------- launch ----------------
extern "C" void kernel_launch(void* const* d_in, const int* in_sizes, int n_in,
                              void* d_out, int out_size)
{
    const float* x   = (const float*)d_in[0];
    const float* Win = (const float*)d_in[1];
    const float* bin = (const float*)d_in[2];
    const float* Wg  = (const float*)d_in[3];
    const float* bgt = (const float*)d_in[4];
    const float* lam = (const float*)d_in[5];
    float* out = (float*)d_out;

    cudaFuncSetAttribute(gates_gemm_hmma, cudaFuncAttributeMaxDynamicSharedMemorySize, SMEM_DYN);

    conv_x<<<(M_ * (D_ / 4)) / 256, 256>>>(x);
    conv_w<<<(D_ * (D_ / 4)) / 256, 256>>>(Win, Wg);

    dim3 ggrid(D_ / BN, M_ / BM);                // (16, 256)
    gates_gemm_hmma<<<ggrid, 256, SMEM_DYN>>>(x, bin, bgt, lam);

    scan_carry<<<B_, 256>>>();                   // 4 blocks
    scan_apply<<<(NCHUNKS * 4 * (D_ / 4 / 64)) / 4, 256>>>(out);  // 1024 blocks
}

// round 8
// speedup vs baseline: 5.5085x; 1.1122x over previous
#include <cuda_runtime.h>
#include <cuda_fp16.h>
#include <math.h>
#include <stdint.h>

// Problem constants (RG_LRU: B=4, T=8192, D=1024, C=8)
#define B_ 4
#define T_ 8192
#define D_ 1024
#define M_ (B_ * T_)          // 32768 rows

// Chunked scan: chunk == GEMM row tile (128 consecutive timesteps)
#define TCHUNK 128
#define NCHK_PER_B (T_ / TCHUNK)      // 64
#define NCHUNKS (M_ / TCHUNK)         // 256

// GEMM tiling
#define BM 128
#define BN 64
#define BK 32                 // fp16 per K-tile = 64 B rows (SW64 atom)
#define KT (D_ / BK)          // 32

// smem stage layout (bytes): x tile 128x64B = 8KB, W tiles 64x64B = 4KB each
#define OFF_X   0
#define OFF_WI  8192
#define OFF_WG  12288
#define STAGE_SZ 16384
#define NSTAGE 5              // 80 KB pipeline

// epilogue scan arrays (union with pipeline stages)
#define AL_STRIDE 66                     // padded row stride (floats)
#define AL_OFF  0                        // alpha  [128][66] = 33792 B
#define XB_OFF  33792                    // xbeta  [128][66] = 33792 B
#define AGG_OFF 67584                    // seg aggregates: 2 x 256 floats = 2 KB
// params live beyond both regions
#define PAR_OFF (NSTAGE * STAGE_SZ)      // 81920
#define SMEM_DYN (PAR_OFF + 768 + 1024)  // ~83.6 KB -> 2 CTAs/SM

// ---------------- device scratch (allocation-free) ----------------
// Packed prefix pairs: h_t = P_t * carry + S_t,  stored as half2(P, S)
__device__ __half2 g_PS[(size_t)M_ * D_];    // 128 MB
__device__ float g_Ac[(size_t)NCHUNKS * D_]; // chunk aggregate products (fp32)
__device__ float g_Bc[(size_t)NCHUNKS * D_]; // chunk aggregate scan values (fp32)
__device__ float g_carry[(size_t)NCHUNKS * D_];
__device__ __half g_xh[(size_t)M_ * D_];     // 64 MB
__device__ __half g_wi[D_ * D_];             // 2 MB
__device__ __half g_wg[D_ * D_];             // 2 MB

// ---------------- helpers ----------------
__device__ __forceinline__ uint32_t smem_u32(const void* p) {
    uint32_t a;
    asm("{ .reg .u64 t; cvta.to.shared.u64 t, %1; cvt.u32.u64 %0, t; }" : "=r"(a) : "l"(p));
    return a;
}
__device__ __forceinline__ void cp16(uint32_t dst, const void* src) {
    asm volatile("cp.async.cg.shared.global [%0], [%1], 16;" :: "r"(dst), "l"(src));
}
#define CP_COMMIT() asm volatile("cp.async.commit_group;" ::: "memory")
#define CP_WAIT(n)  asm volatile("cp.async.wait_group %0;" :: "n"(n) : "memory")

__device__ __forceinline__ void ldsm4(uint32_t addr, uint32_t& r0, uint32_t& r1,
                                      uint32_t& r2, uint32_t& r3) {
    asm volatile("ldmatrix.sync.aligned.m8n8.x4.shared.b16 {%0,%1,%2,%3}, [%4];"
                 : "=r"(r0), "=r"(r1), "=r"(r2), "=r"(r3) : "r"(addr));
}
__device__ __forceinline__ void mma16816(float* d, const uint32_t* a, const uint32_t* b) {
    asm volatile("mma.sync.aligned.m16n8k16.row.col.f32.f16.f16.f32 "
                 "{%0,%1,%2,%3}, {%4,%5,%6,%7}, {%8,%9}, {%0,%1,%2,%3};"
                 : "+f"(d[0]), "+f"(d[1]), "+f"(d[2]), "+f"(d[3])
                 : "r"(a[0]), "r"(a[1]), "r"(a[2]), "r"(a[3]), "r"(b[0]), "r"(b[1]));
}
__device__ __forceinline__ float sigm(float v) { return 1.0f / (1.0f + __expf(-v)); }

// SW64 swizzle for 64B rows: chunk c (16B) at row r -> c ^ ((r>>1)&3)
__device__ __forceinline__ uint32_t sw64_off(int r, int c) {
    return (uint32_t)(r * 64 + ((c ^ ((r >> 1) & 3)) << 4));
}

// ---------------- fp32 -> fp16 conversion kernels ----------------
__global__ void __launch_bounds__(256)
conv_x(const float* __restrict__ x)
{
    size_t i = (size_t)blockIdx.x * 256 + threadIdx.x;   // float4 index
    float4 v = ((const float4*)x)[i];
    ushort4 h;
    h.x = __half_as_ushort(__float2half(v.x));
    h.y = __half_as_ushort(__float2half(v.y));
    h.z = __half_as_ushort(__float2half(v.z));
    h.w = __half_as_ushort(__float2half(v.w));
    ((ushort4*)g_xh)[i] = h;
}

__global__ void __launch_bounds__(256)
conv_w(const float* __restrict__ wi, const float* __restrict__ wg)
{
    size_t i = (size_t)blockIdx.x * 256 + threadIdx.x;
    float4 a = ((const float4*)wi)[i];
    float4 b = ((const float4*)wg)[i];
    ushort4 h;
    h.x = __half_as_ushort(__float2half(a.x));
    h.y = __half_as_ushort(__float2half(a.y));
    h.z = __half_as_ushort(__float2half(a.z));
    h.w = __half_as_ushort(__float2half(a.w));
    ((ushort4*)g_wi)[i] = h;
    h.x = __half_as_ushort(__float2half(b.x));
    h.y = __half_as_ushort(__float2half(b.y));
    h.z = __half_as_ushort(__float2half(b.z));
    h.w = __half_as_ushort(__float2half(b.w));
    ((ushort4*)g_wg)[i] = h;
}

// ---------------- stage loader: gmem -> SW64-swizzled smem ----------------
__device__ __forceinline__ void ld_stage(uint32_t sbase, int kt, int m0, int n0, int tid)
{
    const int k0 = kt * BK;
#pragma unroll
    for (int i = 0; i < 2; i++) {            // x tile: 128 rows x 4 chunks
        int q = tid + i * 256;
        int r = q >> 2, c = q & 3;
        uint32_t off = sw64_off(r, c);
        size_t gi = (size_t)(m0 + r) * D_ + k0 + c * 8;
        cp16(sbase + OFF_X + off, g_xh + gi);
    }
    {                                        // W tiles: 64 rows x 4 chunks
        int q = tid;
        int r = q >> 2, c = q & 3;
        uint32_t off = sw64_off(r, c);
        size_t gi = (size_t)(n0 + r) * D_ + k0 + c * 8;
        cp16(sbase + OFF_WI + off, g_wi + gi);
        cp16(sbase + OFF_WG + off, g_wg + gi);
    }
}

// ---- fused dual-GEMM (HMMA fp16) + gate epilogue + intra-chunk prefix scan ----
__global__ void __launch_bounds__(256, 2)
gates_gemm_hmma(const float* __restrict__ x,
                const float* __restrict__ bin, const float* __restrict__ bgt,
                const float* __restrict__ lam)
{
    extern __shared__ char smem_raw[];
    char* smem = (char*)(((uintptr_t)smem_raw + 1023) & ~(uintptr_t)1023);
    const uint32_t sb = smem_u32(smem);
    const int tid = threadIdx.x;
    const int lane = tid & 31;
    const int wid = tid >> 5;
    const int wm = wid >> 1;                 // 0..3
    const int wn = wid & 1;                  // 0..1
    const int m0 = blockIdx.y * BM;          // chunk start row (within one batch)
    const int n0 = blockIdx.x * BN;

    float* cl_s = (float*)(smem + PAR_OFF);
    float* bi_s = cl_s + 64;
    float* bg_s = bi_s + 64;
    if (tid < 64) {
        float l = lam[n0 + tid];
        cl_s[tid] = 8.0f * log1pf(expf(l));  // C * softplus(lambda)
        bi_s[tid] = bin[n0 + tid];
        bg_s[tid] = bgt[n0 + tid];
    }

    float aig[2][4][4], arg[2][4][4];
#pragma unroll
    for (int mb = 0; mb < 2; mb++)
#pragma unroll
        for (int nb = 0; nb < 4; nb++)
#pragma unroll
            for (int q = 0; q < 4; q++) { aig[mb][nb][q] = 0.f; arg[mb][nb][q] = 0.f; }

    const int r16 = (lane & 7) | (((lane >> 3) & 1) << 3);  // row within 16
    const int coff = lane >> 4;                             // k-chunk offset 0/1
    int arow[2], brow[2];
#pragma unroll
    for (int mb = 0; mb < 2; mb++) arow[mb] = wm * 32 + mb * 16 + r16;
#pragma unroll
    for (int j = 0; j < 2; j++)    brow[j] = wn * 32 + j * 16 + r16;

    // prologue: fill pipeline
#pragma unroll
    for (int s = 0; s < NSTAGE; s++) { ld_stage(sb + s * STAGE_SZ, s, m0, n0, tid); CP_COMMIT(); }

    for (int kt = 0; kt < KT; kt++) {
        const uint32_t stb = sb + (kt % NSTAGE) * STAGE_SZ;
        CP_WAIT(NSTAGE - 1);
        __syncthreads();

#pragma unroll
        for (int k16 = 0; k16 < 2; k16++) {
            const int chunk = k16 * 2 + coff;
            uint32_t ax[2][4];
#pragma unroll
            for (int mb = 0; mb < 2; mb++) {
                uint32_t off = sw64_off(arow[mb], chunk);
                ldsm4(stb + OFF_X + off, ax[mb][0], ax[mb][1], ax[mb][2], ax[mb][3]);
            }
            uint32_t bwi[4][2], bwg[4][2];
#pragma unroll
            for (int j = 0; j < 2; j++) {
                uint32_t off = sw64_off(brow[j], chunk);
                uint32_t r0, r1, r2, r3;
                ldsm4(stb + OFF_WI + off, r0, r1, r2, r3);
                bwi[j * 2 + 0][0] = r0; bwi[j * 2 + 0][1] = r2;
                bwi[j * 2 + 1][0] = r1; bwi[j * 2 + 1][1] = r3;
                ldsm4(stb + OFF_WG + off, r0, r1, r2, r3);
                bwg[j * 2 + 0][0] = r0; bwg[j * 2 + 0][1] = r2;
                bwg[j * 2 + 1][0] = r1; bwg[j * 2 + 1][1] = r3;
            }
#pragma unroll
            for (int mb = 0; mb < 2; mb++)
#pragma unroll
                for (int nb = 0; nb < 4; nb++)
                    mma16816(aig[mb][nb], ax[mb], bwi[nb]);
#pragma unroll
            for (int mb = 0; mb < 2; mb++)
#pragma unroll
                for (int nb = 0; nb < 4; nb++)
                    mma16816(arg[mb][nb], ax[mb], bwg[nb]);
        }
        __syncthreads();
        // Always commit a group (possibly empty) so wait_group(NSTAGE-1)
        // always guarantees the consumed stage has landed.
        const int nk = kt + NSTAGE;
        if (nk < KT) ld_stage(stb, nk, m0, n0, tid);
        CP_COMMIT();
    }

    // -------- epilogue 1: gate math -> smem (reusing dead stage memory) --------
    float* al_s = (float*)(smem + AL_OFF);   // [128][AL_STRIDE]
    float* xb_s = (float*)(smem + XB_OFF);
    const int g = lane >> 2;
    const int t2 = 2 * (lane & 3);
#pragma unroll
    for (int mb = 0; mb < 2; mb++) {
#pragma unroll
        for (int half = 0; half < 2; half++) {
            const int rl = wm * 32 + mb * 16 + g + half * 8;   // 0..127
#pragma unroll
            for (int nb = 0; nb < 4; nb++) {
                const int cloc = wn * 32 + nb * 8 + t2;        // 0..63
                const size_t gi = (size_t)(m0 + rl) * D_ + n0 + cloc;
                float2 xv = *(const float2*)(x + gi);
                float a2[2], v2[2];
#pragma unroll
                for (int q = 0; q < 2; q++) {
                    float ig = aig[mb][nb][half * 2 + q] + bi_s[cloc + q];
                    float rg = arg[mb][nb][half * 2 + q] + bg_s[cloc + q];
                    float sr = sigm(rg);
                    float al = __expf(-cl_s[cloc + q] * sr);
                    float be = sqrtf(fmaxf(1.0f - al * al + 1e-6f, 0.0f));
                    a2[q] = al;
                    v2[q] = be * sigm(ig) * ((q == 0) ? xv.x : xv.y);
                }
                *(float2*)(al_s + rl * AL_STRIDE + cloc) = make_float2(a2[0], a2[1]);
                *(float2*)(xb_s + rl * AL_STRIDE + cloc) = make_float2(v2[0], v2[1]);
            }
        }
    }
    __syncthreads();

    // -------- epilogue 2: intra-chunk prefix scan (h_t = P_t*carry + S_t) --------
    const int seg = tid >> 6;        // 4 segments of 32 timesteps
    const int ch  = tid & 63;        // channel within tile
    float P = 1.f, S = 0.f;
#pragma unroll 8
    for (int s = 0; s < 32; s++) {
        float a = al_s[(seg * 32 + s) * AL_STRIDE + ch];
        float v = xb_s[(seg * 32 + s) * AL_STRIDE + ch];
        S = fmaf(a, S, v);
        P *= a;
    }
    float* aggP = (float*)(smem + AGG_OFF);
    float* aggS = aggP + 256;
    aggP[seg * 64 + ch] = P;
    aggS[seg * 64 + ch] = S;
    __syncthreads();
    float Pc = 1.f, Sc = 0.f;
#pragma unroll
    for (int q = 0; q < 3; q++) {
        if (q < seg) {
            float pq = aggP[q * 64 + ch], sq = aggS[q * 64 + ch];
            Sc = fmaf(pq, Sc, sq);
            Pc *= pq;
        }
    }
    P = Pc; S = Sc;
#pragma unroll 8
    for (int s = 0; s < 32; s++) {
        const int rl = seg * 32 + s;
        float a = al_s[rl * AL_STRIDE + ch];
        float v = xb_s[rl * AL_STRIDE + ch];
        P *= a;
        S = fmaf(a, S, v);
        const size_t gi = (size_t)(m0 + rl) * D_ + n0 + ch;
        g_PS[gi] = __floats2half2_rn(P, S);   // packed fp16 prefix pair
    }
    if (seg == 3) {
        const size_t ci = (size_t)blockIdx.y * D_ + n0 + ch;
        g_Ac[ci] = P;    // fp32 aggregates (carry chain stays exact-ish)
        g_Bc[ci] = S;
    }
}

// ------- carry scan over chunk aggregates (batched prefetch, MLP=16) -------
__global__ void __launch_bounds__(256)
scan_carry()
{
    const int b = blockIdx.x;                 // 0..3 (batch)
    const int d4 = threadIdx.x;               // 0..255 (float4 channel group)
    float4 h = make_float4(0.f, 0.f, 0.f, 0.f);
    for (int base = 0; base < NCHK_PER_B; base += 8) {
        float4 a[8], v[8];
#pragma unroll
        for (int j = 0; j < 8; j++) {
            const size_t i = (size_t)(b * NCHK_PER_B + base + j) * (D_ / 4) + d4;
            a[j] = ((const float4*)g_Ac)[i];
            v[j] = ((const float4*)g_Bc)[i];
        }
#pragma unroll
        for (int j = 0; j < 8; j++) {
            const size_t i = (size_t)(b * NCHK_PER_B + base + j) * (D_ / 4) + d4;
            ((float4*)g_carry)[i] = h;
            h.x = fmaf(a[j].x, h.x, v[j].x);
            h.y = fmaf(a[j].y, h.y, v[j].y);
            h.z = fmaf(a[j].z, h.z, v[j].z);
            h.w = fmaf(a[j].w, h.w, v[j].w);
        }
    }
}

// ---------------- elementwise apply: out = P*carry + S ----------------
__global__ void __launch_bounds__(256)
scan_apply(float* __restrict__ out)
{
    const int gid = blockIdx.x * 256 + threadIdx.x;    // 0 .. 262143
    const int cid = gid >> 10;                         // chunk 0..255
    const int seg = (gid >> 8) & 3;                    // 32-step segment
    const int d4  = gid & 255;

    const float4 c = ((const float4*)g_carry)[(size_t)cid * (D_ / 4) + d4];
    size_t fi = (size_t)(cid * TCHUNK + seg * 32) * (D_ / 4) + d4;
#pragma unroll 4
    for (int s = 0; s < 32; s++) {
        uint4 w = ((const uint4*)g_PS)[fi];            // 4 x half2(P,S)
        float2 e0 = __half22float2(*(__half2*)&w.x);
        float2 e1 = __half22float2(*(__half2*)&w.y);
        float2 e2 = __half22float2(*(__half2*)&w.z);
        float2 e3 = __half22float2(*(__half2*)&w.w);
        float4 o;
        o.x = fmaf(e0.x, c.x, e0.y);
        o.y = fmaf(e1.x, c.y, e1.y);
        o.z = fmaf(e2.x, c.z, e2.y);
        o.w = fmaf(e3.x, c.w, e3.y);
        ((float4*)out)[fi] = o;
        fi += D_ / 4;
    }
}

// ---------------- launch ----------------
extern "C" void kernel_launch(void* const* d_in, const int* in_sizes, int n_in,
                              void* d_out, int out_size)
{
    const float* x   = (const float*)d_in[0];
    const float* Win = (const float*)d_in[1];
    const float* bin = (const float*)d_in[2];
    const float* Wg  = (const float*)d_in[3];
    const float* bgt = (const float*)d_in[4];
    const float* lam = (const float*)d_in[5];
    float* out = (float*)d_out;

    cudaFuncSetAttribute(gates_gemm_hmma, cudaFuncAttributeMaxDynamicSharedMemorySize, SMEM_DYN);

    conv_x<<<(M_ * (D_ / 4)) / 256, 256>>>(x);
    conv_w<<<(D_ * (D_ / 4)) / 256, 256>>>(Win, Wg);

    dim3 ggrid(D_ / BN, M_ / BM);                // (16, 256)
    gates_gemm_hmma<<<ggrid, 256, SMEM_DYN>>>(x, bin, bgt, lam);

    scan_carry<<<B_, 256>>>();                   // 4 blocks
    scan_apply<<<1024, 256>>>(out);
}